// round 10
// baseline (speedup 1.0000x reference)
#include <cuda_runtime.h>
#include <cuda_bf16.h>

#define DIMC 1024
#define NHEAD 16
#define HDIM 64
#define BB 4
#define TT 2048
#define MROWS (BB * TT)   // 8192

// Scratch (device globals — allocation-free contract)
__device__ float g_q[BB * NHEAD * TT * HDIM];   // [B,H,T,D]
__device__ float g_k[BB * NHEAD * TT * HDIM];
__device__ float g_v[BB * NHEAD * TT * HDIM];
__device__ float g_att[MROWS * DIMC];           // [B*T, C] attn out (tf32 bits)
__device__ unsigned g_xc[MROWS * DIMC];         // tf32-rounded x
__device__ unsigned g_wc[4 * DIMC * DIMC];      // tf32-rounded wq|wk|wv|wo

__device__ __forceinline__ unsigned f2tf32(float x) {
    unsigned u;
    asm("cvt.rna.tf32.f32 %0, %1;" : "=r"(u) : "f"(x));
    return u;
}

// 2^x on the FMA/ALU pipes (no MUFU). x <= 0 expected; clamped at -120.
__device__ __forceinline__ float exp2_fast(float x) {
    x = fmaxf(x, -120.f);
    float n = floorf(x);
    float f = x - n;                 // [0,1)
    float p = 1.78656e-4f;           // ~(ln2)^6/720
    p = fmaf(p, f, 1.33336e-3f);
    p = fmaf(p, f, 9.61813e-3f);
    p = fmaf(p, f, 5.55041e-2f);
    p = fmaf(p, f, 2.40226507e-1f);
    p = fmaf(p, f, 6.93147181e-1f);
    p = fmaf(p, f, 1.0f);
    return __uint_as_float(__float_as_uint(p) + (((int)n) << 23));
}

#define MMA_TF32(d, a, b)                                                    \
    asm volatile("mma.sync.aligned.m16n8k8.row.col.f32.tf32.tf32.f32 "        \
                 "{%0,%1,%2,%3}, {%4,%5,%6,%7}, {%8,%9}, {%0,%1,%2,%3};"      \
                 : "+f"(d[0]), "+f"(d[1]), "+f"(d[2]), "+f"(d[3])             \
                 : "r"(a[0]), "r"(a[1]), "r"(a[2]), "r"(a[3]),                \
                   "r"(b[0]), "r"(b[1]))

// ---------------------------------------------------------------------------
// Prepass: tf32-round x and the four weights into unsigned scratch.
// ---------------------------------------------------------------------------
#define XF4  (MROWS * DIMC / 4)        // 2097152
#define WF4  (DIMC * DIMC / 4)         // 262144

__global__ __launch_bounds__(256) void conv_in_kernel(
    const float* __restrict__ x,
    const float* __restrict__ wq, const float* __restrict__ wk,
    const float* __restrict__ wv, const float* __restrict__ wo)
{
    int i = blockIdx.x * 256 + threadIdx.x;     // one float4 per thread
    const float* src;
    unsigned* dst;
    int off;
    if (i < XF4) { src = x; dst = g_xc; off = i; }
    else {
        int j = i - XF4;
        int seg = j >> 18;                       // /262144
        off = j & (WF4 - 1);
        src = seg == 0 ? wq : seg == 1 ? wk : seg == 2 ? wv : wo;
        dst = g_wc + seg * (DIMC * DIMC);
    }
    float4 v = *(const float4*)(src + (size_t)off * 4);
    *(uint4*)(dst + (size_t)off * 4) =
        make_uint4(f2tf32(v.x), f2tf32(v.y), f2tf32(v.z), f2tf32(v.w));
}

// ---------------------------------------------------------------------------
// TF32 tensor-core GEMM (unchanged from R9): 128x128 block, BK=16/stage,
// 256 threads (8 warps, 2x4 grid, 64x32/warp), k-major KSTRIDE=136 smem,
// double-buffered. qkv_mode scatters to [B,H,T,D].
// ---------------------------------------------------------------------------
#define KSTRIDE 136

__global__ __launch_bounds__(256, 2) void gemm_kernel(
    const unsigned* __restrict__ A,
    const unsigned* __restrict__ W0, const unsigned* __restrict__ W1,
    const unsigned* __restrict__ W2,
    float* __restrict__ D0, float* __restrict__ D1, float* __restrict__ D2,
    int qkv_mode)
{
    __shared__ unsigned As[2][16][KSTRIDE];
    __shared__ unsigned Bs[2][16][KSTRIDE];

    const unsigned* W = W0;
    float* D = D0;
    if (blockIdx.z == 1) { W = W1; D = D1; }
    else if (blockIdx.z == 2) { W = W2; D = D2; }

    const int tid  = threadIdx.x;
    const int lane = tid & 31;
    const int w    = tid >> 5;
    const int wm   = w >> 2;
    const int wn   = w & 3;
    const int r0 = blockIdx.y * 128;
    const int c0 = blockIdx.x * 128;

    const int lrow = tid >> 1;
    const int lk   = (tid & 1) * 8;
    const unsigned* Ap = A + (size_t)(r0 + lrow) * DIMC + lk;
    const unsigned* Wp = W + (size_t)(c0 + lrow) * DIMC + lk;

    const int fr = lane >> 2;
    const int fc = lane & 3;

    float acc[4][4][4];
#pragma unroll
    for (int mi = 0; mi < 4; mi++)
#pragma unroll
        for (int ni = 0; ni < 4; ni++)
#pragma unroll
            for (int e = 0; e < 4; e++) acc[mi][ni][e] = 0.f;

    {
        uint4 a0 = *(const uint4*)(Ap);
        uint4 a1 = *(const uint4*)(Ap + 4);
        uint4 b0 = *(const uint4*)(Wp);
        uint4 b1 = *(const uint4*)(Wp + 4);
        As[0][lk + 0][lrow] = a0.x; As[0][lk + 1][lrow] = a0.y;
        As[0][lk + 2][lrow] = a0.z; As[0][lk + 3][lrow] = a0.w;
        As[0][lk + 4][lrow] = a1.x; As[0][lk + 5][lrow] = a1.y;
        As[0][lk + 6][lrow] = a1.z; As[0][lk + 7][lrow] = a1.w;
        Bs[0][lk + 0][lrow] = b0.x; Bs[0][lk + 1][lrow] = b0.y;
        Bs[0][lk + 2][lrow] = b0.z; Bs[0][lk + 3][lrow] = b0.w;
        Bs[0][lk + 4][lrow] = b1.x; Bs[0][lk + 5][lrow] = b1.y;
        Bs[0][lk + 6][lrow] = b1.z; Bs[0][lk + 7][lrow] = b1.w;
    }
    __syncthreads();

    int buf = 0;
    for (int kt = 1; kt <= DIMC / 16; kt++) {
        uint4 a0, a1, b0, b1;
        const bool more = (kt < DIMC / 16);
        if (more) {
            a0 = *(const uint4*)(Ap + kt * 16);
            a1 = *(const uint4*)(Ap + kt * 16 + 4);
            b0 = *(const uint4*)(Wp + kt * 16);
            b1 = *(const uint4*)(Wp + kt * 16 + 4);
        }

#pragma unroll
        for (int kk = 0; kk < 2; kk++) {
            unsigned af[4][4], bfr[4][2];
#pragma unroll
            for (int mi = 0; mi < 4; mi++) {
                int r = wm * 64 + mi * 16 + fr;
                af[mi][0] = As[buf][kk * 8 + fc][r];
                af[mi][1] = As[buf][kk * 8 + fc][r + 8];
                af[mi][2] = As[buf][kk * 8 + fc + 4][r];
                af[mi][3] = As[buf][kk * 8 + fc + 4][r + 8];
            }
#pragma unroll
            for (int ni = 0; ni < 4; ni++) {
                int n = wn * 32 + ni * 8 + fr;
                bfr[ni][0] = Bs[buf][kk * 8 + fc][n];
                bfr[ni][1] = Bs[buf][kk * 8 + fc + 4][n];
            }
#pragma unroll
            for (int mi = 0; mi < 4; mi++)
#pragma unroll
                for (int ni = 0; ni < 4; ni++)
                    MMA_TF32(acc[mi][ni], af[mi], bfr[ni]);
        }

        if (more) {
            int nb = buf ^ 1;
            As[nb][lk + 0][lrow] = a0.x; As[nb][lk + 1][lrow] = a0.y;
            As[nb][lk + 2][lrow] = a0.z; As[nb][lk + 3][lrow] = a0.w;
            As[nb][lk + 4][lrow] = a1.x; As[nb][lk + 5][lrow] = a1.y;
            As[nb][lk + 6][lrow] = a1.z; As[nb][lk + 7][lrow] = a1.w;
            Bs[nb][lk + 0][lrow] = b0.x; Bs[nb][lk + 1][lrow] = b0.y;
            Bs[nb][lk + 2][lrow] = b0.z; Bs[nb][lk + 3][lrow] = b0.w;
            Bs[nb][lk + 4][lrow] = b1.x; Bs[nb][lk + 5][lrow] = b1.y;
            Bs[nb][lk + 6][lrow] = b1.z; Bs[nb][lk + 7][lrow] = b1.w;
            __syncthreads();
            buf ^= 1;
        }
    }

    if (!qkv_mode) {
#pragma unroll
        for (int mi = 0; mi < 4; mi++) {
            int r = r0 + wm * 64 + mi * 16 + fr;
#pragma unroll
            for (int ni = 0; ni < 4; ni++) {
                int c = c0 + wn * 32 + ni * 8 + fc * 2;
                *(float2*)(D + (size_t)r * DIMC + c) =
                    make_float2(acc[mi][ni][0], acc[mi][ni][1]);
                *(float2*)(D + (size_t)(r + 8) * DIMC + c) =
                    make_float2(acc[mi][ni][2], acc[mi][ni][3]);
            }
        }
    } else {
#pragma unroll
        for (int mi = 0; mi < 4; mi++) {
            int row = r0 + wm * 64 + mi * 16 + fr;
#pragma unroll
            for (int half = 0; half < 2; half++) {
                int rr = row + half * 8;
                int b = rr >> 11;
                int t = rr & 2047;
#pragma unroll
                for (int ni = 0; ni < 4; ni++) {
                    int cc = wn * 32 + ni * 8 + fc * 2;
                    int h = blockIdx.x * 2 + (cc >> 6);
                    int d = cc & 63;
                    size_t idx = (((size_t)(b * NHEAD + h) * TT + t) * HDIM) + d;
                    *(float2*)(D + idx) =
                        make_float2(acc[mi][ni][half * 2 + 0],
                                    acc[mi][ni][half * 2 + 1]);
                }
            }
        }
    }
}

// ---------------------------------------------------------------------------
// Flash attention, tensor-core, BQ=256: 8 warps, each owns 32 rows
// (2 m-atoms) x 64 cols. K/V fragments shared across 2 m-atoms -> 1.5 LDS
// per MMA (was 2.5). Warp-local softmax; warp-private P rows; 2 CTA
// syncs/tile amortized over 256 rows. Epilogue stores tf32 bits.
// ---------------------------------------------------------------------------
#define ASTRIDE 68
#define BQ 256

__global__ __launch_bounds__(256) void attn_kernel()
{
    extern __shared__ unsigned smu[];
    unsigned* Qs = smu;                    // [256][68] tf32, scaled by 0.125*log2e
    unsigned* Ks = Qs + BQ * ASTRIDE;      // [64][68]  tf32, [key][d]
    unsigned* Vt = Ks + 64 * ASTRIDE;      // [64][68]  tf32, [d][key]
    unsigned* Ps = Vt + 64 * ASTRIDE;      // [256][68] tf32 probs (warp-private rows)

    const int tid  = threadIdx.x;
    const int lane = tid & 31;
    const int w    = tid >> 5;        // warp owns rows w*32 .. w*32+31
    const int fr   = lane >> 2;       // 0..7
    const int fc   = lane & 3;        // 0..3

    const int bh = blockIdx.y;
    const int q0 = (gridDim.x - 1 - blockIdx.x) * BQ;    // heavy tiles first

    const float* Q = g_q + (size_t)bh * TT * HDIM;
    const float* K = g_k + (size_t)bh * TT * HDIM;
    const float* V = g_v + (size_t)bh * TT * HDIM;

    const float qsc = 0.125f * 1.4426950408889634f;  // scale * log2(e)

    // Stage Q (tf32, scaled): 256 x 64
#pragma unroll
    for (int it = 0; it < 16; it++) {
        int e = tid + it * 256;
        int r = e >> 4, dq = (e & 15) * 4;
        float4 v4 = *(const float4*)(Q + (size_t)(q0 + r) * HDIM + dq);
        unsigned* p = &Qs[r * ASTRIDE + dq];
        p[0] = f2tf32(v4.x * qsc); p[1] = f2tf32(v4.y * qsc);
        p[2] = f2tf32(v4.z * qsc); p[3] = f2tf32(v4.w * qsc);
    }

    // O: 2 m-atoms x 8 n-atoms; m/l for 4 row-slots (mi,h)
    float O[2][8][4];
#pragma unroll
    for (int mi = 0; mi < 2; mi++)
#pragma unroll
        for (int ni = 0; ni < 8; ni++)
#pragma unroll
            for (int e = 0; e < 4; e++) O[mi][ni][e] = 0.f;
    float m_i[4], l_i[4];
#pragma unroll
    for (int s = 0; s < 4; s++) { m_i[s] = -1e30f; l_i[s] = 0.f; }

    const int rw = w * 32;                 // warp row base
    const int ntiles = (q0 >> 6) + 4;

    for (int kt = 0; kt < ntiles; kt++) {
        const int k0 = kt * 64;
        __syncthreads();

        // Stage K: Ks[key][d]
#pragma unroll
        for (int it = 0; it < 4; it++) {
            int e = tid + it * 256;
            int k = e >> 4, dq = (e & 15) * 4;
            float4 kv = *(const float4*)(K + (size_t)(k0 + k) * HDIM + dq);
            unsigned* p = &Ks[k * ASTRIDE + dq];
            p[0] = f2tf32(kv.x); p[1] = f2tf32(kv.y);
            p[2] = f2tf32(kv.z); p[3] = f2tf32(kv.w);
        }
        // Stage V transposed: Vt[d][key]
#pragma unroll
        for (int it = 0; it < 4; it++) {
            int e = tid + it * 256;
            int d = e & 63;
            int kq = (e >> 6) * 4;
            float v0 = V[(size_t)(k0 + kq + 0) * HDIM + d];
            float v1 = V[(size_t)(k0 + kq + 1) * HDIM + d];
            float v2 = V[(size_t)(k0 + kq + 2) * HDIM + d];
            float v3 = V[(size_t)(k0 + kq + 3) * HDIM + d];
            *(uint4*)&Vt[d * ASTRIDE + kq] =
                make_uint4(f2tf32(v0), f2tf32(v1), f2tf32(v2), f2tf32(v3));
        }
        __syncthreads();

        // S = Qs @ Ks^T : warp computes 32 rows x 64 cols
        float sacc[2][8][4];
#pragma unroll
        for (int mi = 0; mi < 2; mi++)
#pragma unroll
            for (int ni = 0; ni < 8; ni++)
#pragma unroll
                for (int e = 0; e < 4; e++) sacc[mi][ni][e] = 0.f;

#pragma unroll
        for (int kk = 0; kk < 8; kk++) {
            unsigned af[2][4];
#pragma unroll
            for (int mi = 0; mi < 2; mi++) {
                const unsigned* b = &Qs[(rw + mi * 16 + fr) * ASTRIDE + kk * 8 + fc];
                af[mi][0] = b[0];
                af[mi][1] = b[8 * ASTRIDE];
                af[mi][2] = b[4];
                af[mi][3] = b[8 * ASTRIDE + 4];
            }
#pragma unroll
            for (int ni = 0; ni < 8; ni++) {
                const unsigned* b = &Ks[(ni * 8 + fr) * ASTRIDE + kk * 8 + fc];
                unsigned bf[2] = {b[0], b[4]};
#pragma unroll
                for (int mi = 0; mi < 2; mi++)
                    MMA_TF32(sacc[mi][ni], af[mi], bf);
            }
        }

        // Warp-local softmax (log2 domain), 4 row-slots
        const bool need_mask = (k0 + 63 > q0);
#pragma unroll
        for (int mi = 0; mi < 2; mi++)
#pragma unroll
        for (int h = 0; h < 2; h++) {
            const int slot = mi * 2 + h;
            const int r = rw + mi * 16 + fr + h * 8;
            const int rg = q0 + r;
            float rm = -1e30f;
#pragma unroll
            for (int ni = 0; ni < 8; ni++)
#pragma unroll
            for (int e = 0; e < 2; e++) {
                float s = sacc[mi][ni][h * 2 + e];
                if (need_mask && (k0 + ni * 8 + fc * 2 + e > rg)) s = -1e30f;
                sacc[mi][ni][h * 2 + e] = s;
                rm = fmaxf(rm, s);
            }
            rm = fmaxf(rm, __shfl_xor_sync(0xffffffffu, rm, 1));
            rm = fmaxf(rm, __shfl_xor_sync(0xffffffffu, rm, 2));
            float mnew = fmaxf(m_i[slot], rm);
            float al = exp2_fast(m_i[slot] - mnew);
            m_i[slot] = mnew;
            float rs = 0.f;
#pragma unroll
            for (int ni = 0; ni < 8; ni++) {
                float p0 = exp2_fast(sacc[mi][ni][h * 2 + 0] - mnew);
                float p1 = exp2_fast(sacc[mi][ni][h * 2 + 1] - mnew);
                rs += p0 + p1;
                *(uint2*)&Ps[r * ASTRIDE + ni * 8 + fc * 2] =
                    make_uint2(f2tf32(p0), f2tf32(p1));
            }
            rs += __shfl_xor_sync(0xffffffffu, rs, 1);
            rs += __shfl_xor_sync(0xffffffffu, rs, 2);
            l_i[slot] = l_i[slot] * al + rs;
#pragma unroll
            for (int ni = 0; ni < 8; ni++) {
                O[mi][ni][h * 2 + 0] *= al;
                O[mi][ni][h * 2 + 1] *= al;
            }
        }
        __syncwarp();

        // O += P @ V
#pragma unroll
        for (int kk = 0; kk < 8; kk++) {
            unsigned af[2][4];
#pragma unroll
            for (int mi = 0; mi < 2; mi++) {
                const unsigned* b = &Ps[(rw + mi * 16 + fr) * ASTRIDE + kk * 8 + fc];
                af[mi][0] = b[0];
                af[mi][1] = b[8 * ASTRIDE];
                af[mi][2] = b[4];
                af[mi][3] = b[8 * ASTRIDE + 4];
            }
#pragma unroll
            for (int ni = 0; ni < 8; ni++) {
                const unsigned* b = &Vt[(ni * 8 + fr) * ASTRIDE + kk * 8 + fc];
                unsigned bf[2] = {b[0], b[4]};
#pragma unroll
                for (int mi = 0; mi < 2; mi++)
                    MMA_TF32(O[mi][ni], af[mi], bf);
            }
        }
    }

    // Epilogue: normalize, store tf32-rounded bits to [B*T, C]
    const int b = bh >> 4;
    const int h = bh & 15;
#pragma unroll
    for (int mi = 0; mi < 2; mi++)
#pragma unroll
    for (int hh = 0; hh < 2; hh++) {
        const int slot = mi * 2 + hh;
        float linv = 1.0f / l_i[slot];
        int row = q0 + rw + mi * 16 + fr + hh * 8;
        unsigned* op = (unsigned*)g_att + ((size_t)(b * TT) + row) * DIMC + h * HDIM;
#pragma unroll
        for (int ni = 0; ni < 8; ni++) {
            *(uint2*)(op + ni * 8 + fc * 2) =
                make_uint2(f2tf32(O[mi][ni][hh * 2 + 0] * linv),
                           f2tf32(O[mi][ni][hh * 2 + 1] * linv));
        }
    }
}

#define ATTN_SMEM_BYTES ((BQ*ASTRIDE + 64*ASTRIDE + 64*ASTRIDE + BQ*ASTRIDE) * 4)

// ---------------------------------------------------------------------------
extern "C" void kernel_launch(void* const* d_in, const int* in_sizes, int n_in,
                              void* d_out, int out_size)
{
    const float* x  = (const float*)d_in[0];
    // d_in[1] = mask (unused; causal applied analytically)
    const float* wq = (const float*)d_in[2];
    const float* wk = (const float*)d_in[3];
    const float* wv = (const float*)d_in[4];
    const float* wo = (const float*)d_in[5];
    float* out = (float*)d_out;

    float *dq, *dk, *dv, *datt;
    unsigned *dxc, *dwc;
    cudaGetSymbolAddress((void**)&dq,   g_q);
    cudaGetSymbolAddress((void**)&dk,   g_k);
    cudaGetSymbolAddress((void**)&dv,   g_v);
    cudaGetSymbolAddress((void**)&datt, g_att);
    cudaGetSymbolAddress((void**)&dxc,  g_xc);
    cudaGetSymbolAddress((void**)&dwc,  g_wc);

    cudaFuncSetAttribute(attn_kernel,
                         cudaFuncAttributeMaxDynamicSharedMemorySize,
                         ATTN_SMEM_BYTES);

    // Prepass: round x + weights to tf32
    conv_in_kernel<<<(XF4 + 4 * WF4) / 256, 256>>>(x, wq, wk, wv, wo);

    // QKV projections: 128x128 tiles, grid (8, 64, 3)
    gemm_kernel<<<dim3(8, 64, 3), 256>>>(
        dxc, dwc, dwc + DIMC * DIMC, dwc + 2 * DIMC * DIMC,
        dq, dk, dv, 1);

    // Flash attention: grid (8 q-tiles of 256, 64 b*h)
    attn_kernel<<<dim3(8, 64), 256, ATTN_SMEM_BYTES>>>();

    // Output projection (g_att already holds tf32 bits)
    gemm_kernel<<<dim3(8, 64, 1), 256>>>(
        (unsigned*)datt, dwc + 3 * DIMC * DIMC, nullptr, nullptr,
        out, nullptr, nullptr, 0);
}

// round 11
// speedup vs baseline: 1.0517x; 1.0517x over previous
#include <cuda_runtime.h>
#include <cuda_bf16.h>

#define DIMC 1024
#define NHEAD 16
#define HDIM 64
#define BB 4
#define TT 2048
#define MROWS (BB * TT)   // 8192

// Scratch (device globals — allocation-free contract)
__device__ float g_q[BB * NHEAD * TT * HDIM];   // [B,H,T,D]
__device__ float g_k[BB * NHEAD * TT * HDIM];
__device__ float g_v[BB * NHEAD * TT * HDIM];
__device__ float g_att[MROWS * DIMC];           // [B*T, C] attn out (tf32 bits)
__device__ unsigned g_xc[MROWS * DIMC];         // tf32-rounded x
__device__ unsigned g_wc[4 * DIMC * DIMC];      // tf32-rounded wq|wk|wv|wo

__device__ __forceinline__ unsigned f2tf32(float x) {
    unsigned u;
    asm("cvt.rna.tf32.f32 %0, %1;" : "=r"(u) : "f"(x));
    return u;
}

// 2^x on the FMA/ALU pipes (no MUFU). x <= 0 expected; clamped at -120.
__device__ __forceinline__ float exp2_fast(float x) {
    x = fmaxf(x, -120.f);
    float n = floorf(x);
    float f = x - n;                 // [0,1)
    float p = 1.78656e-4f;           // ~(ln2)^6/720
    p = fmaf(p, f, 1.33336e-3f);
    p = fmaf(p, f, 9.61813e-3f);
    p = fmaf(p, f, 5.55041e-2f);
    p = fmaf(p, f, 2.40226507e-1f);
    p = fmaf(p, f, 6.93147181e-1f);
    p = fmaf(p, f, 1.0f);
    return __uint_as_float(__float_as_uint(p) + (((int)n) << 23));
}

#define MMA_TF32(d, a, b)                                                    \
    asm volatile("mma.sync.aligned.m16n8k8.row.col.f32.tf32.tf32.f32 "        \
                 "{%0,%1,%2,%3}, {%4,%5,%6,%7}, {%8,%9}, {%0,%1,%2,%3};"      \
                 : "+f"(d[0]), "+f"(d[1]), "+f"(d[2]), "+f"(d[3])             \
                 : "r"(a[0]), "r"(a[1]), "r"(a[2]), "r"(a[3]),                \
                   "r"(b[0]), "r"(b[1]))

// ---------------------------------------------------------------------------
// Prepass: tf32-round x and the four weights into unsigned scratch.
// ---------------------------------------------------------------------------
#define XF4  (MROWS * DIMC / 4)        // 2097152
#define WF4  (DIMC * DIMC / 4)         // 262144

__global__ __launch_bounds__(256) void conv_in_kernel(
    const float* __restrict__ x,
    const float* __restrict__ wq, const float* __restrict__ wk,
    const float* __restrict__ wv, const float* __restrict__ wo)
{
    int i = blockIdx.x * 256 + threadIdx.x;     // one float4 per thread
    const float* src;
    unsigned* dst;
    int off;
    if (i < XF4) { src = x; dst = g_xc; off = i; }
    else {
        int j = i - XF4;
        int seg = j >> 18;                       // /262144
        off = j & (WF4 - 1);
        src = seg == 0 ? wq : seg == 1 ? wk : seg == 2 ? wv : wo;
        dst = g_wc + seg * (DIMC * DIMC);
    }
    float4 v = *(const float4*)(src + (size_t)off * 4);
    *(uint4*)(dst + (size_t)off * 4) =
        make_uint4(f2tf32(v.x), f2tf32(v.y), f2tf32(v.z), f2tf32(v.w));
}

// ---------------------------------------------------------------------------
// TF32 tensor-core GEMM (unchanged from R9): 128x128 block, BK=16/stage,
// 256 threads (8 warps, 2x4 grid, 64x32/warp), k-major KSTRIDE=136 smem,
// double-buffered. qkv_mode scatters to [B,H,T,D].
// ---------------------------------------------------------------------------
#define KSTRIDE 136

__global__ __launch_bounds__(256, 2) void gemm_kernel(
    const unsigned* __restrict__ A,
    const unsigned* __restrict__ W0, const unsigned* __restrict__ W1,
    const unsigned* __restrict__ W2,
    float* __restrict__ D0, float* __restrict__ D1, float* __restrict__ D2,
    int qkv_mode)
{
    __shared__ unsigned As[2][16][KSTRIDE];
    __shared__ unsigned Bs[2][16][KSTRIDE];

    const unsigned* W = W0;
    float* D = D0;
    if (blockIdx.z == 1) { W = W1; D = D1; }
    else if (blockIdx.z == 2) { W = W2; D = D2; }

    const int tid  = threadIdx.x;
    const int lane = tid & 31;
    const int w    = tid >> 5;
    const int wm   = w >> 2;
    const int wn   = w & 3;
    const int r0 = blockIdx.y * 128;
    const int c0 = blockIdx.x * 128;

    const int lrow = tid >> 1;
    const int lk   = (tid & 1) * 8;
    const unsigned* Ap = A + (size_t)(r0 + lrow) * DIMC + lk;
    const unsigned* Wp = W + (size_t)(c0 + lrow) * DIMC + lk;

    const int fr = lane >> 2;
    const int fc = lane & 3;

    float acc[4][4][4];
#pragma unroll
    for (int mi = 0; mi < 4; mi++)
#pragma unroll
        for (int ni = 0; ni < 4; ni++)
#pragma unroll
            for (int e = 0; e < 4; e++) acc[mi][ni][e] = 0.f;

    {
        uint4 a0 = *(const uint4*)(Ap);
        uint4 a1 = *(const uint4*)(Ap + 4);
        uint4 b0 = *(const uint4*)(Wp);
        uint4 b1 = *(const uint4*)(Wp + 4);
        As[0][lk + 0][lrow] = a0.x; As[0][lk + 1][lrow] = a0.y;
        As[0][lk + 2][lrow] = a0.z; As[0][lk + 3][lrow] = a0.w;
        As[0][lk + 4][lrow] = a1.x; As[0][lk + 5][lrow] = a1.y;
        As[0][lk + 6][lrow] = a1.z; As[0][lk + 7][lrow] = a1.w;
        Bs[0][lk + 0][lrow] = b0.x; Bs[0][lk + 1][lrow] = b0.y;
        Bs[0][lk + 2][lrow] = b0.z; Bs[0][lk + 3][lrow] = b0.w;
        Bs[0][lk + 4][lrow] = b1.x; Bs[0][lk + 5][lrow] = b1.y;
        Bs[0][lk + 6][lrow] = b1.z; Bs[0][lk + 7][lrow] = b1.w;
    }
    __syncthreads();

    int buf = 0;
    for (int kt = 1; kt <= DIMC / 16; kt++) {
        uint4 a0, a1, b0, b1;
        const bool more = (kt < DIMC / 16);
        if (more) {
            a0 = *(const uint4*)(Ap + kt * 16);
            a1 = *(const uint4*)(Ap + kt * 16 + 4);
            b0 = *(const uint4*)(Wp + kt * 16);
            b1 = *(const uint4*)(Wp + kt * 16 + 4);
        }

#pragma unroll
        for (int kk = 0; kk < 2; kk++) {
            unsigned af[4][4], bfr[4][2];
#pragma unroll
            for (int mi = 0; mi < 4; mi++) {
                int r = wm * 64 + mi * 16 + fr;
                af[mi][0] = As[buf][kk * 8 + fc][r];
                af[mi][1] = As[buf][kk * 8 + fc][r + 8];
                af[mi][2] = As[buf][kk * 8 + fc + 4][r];
                af[mi][3] = As[buf][kk * 8 + fc + 4][r + 8];
            }
#pragma unroll
            for (int ni = 0; ni < 4; ni++) {
                int n = wn * 32 + ni * 8 + fr;
                bfr[ni][0] = Bs[buf][kk * 8 + fc][n];
                bfr[ni][1] = Bs[buf][kk * 8 + fc + 4][n];
            }
#pragma unroll
            for (int mi = 0; mi < 4; mi++)
#pragma unroll
                for (int ni = 0; ni < 4; ni++)
                    MMA_TF32(acc[mi][ni], af[mi], bfr[ni]);
        }

        if (more) {
            int nb = buf ^ 1;
            As[nb][lk + 0][lrow] = a0.x; As[nb][lk + 1][lrow] = a0.y;
            As[nb][lk + 2][lrow] = a0.z; As[nb][lk + 3][lrow] = a0.w;
            As[nb][lk + 4][lrow] = a1.x; As[nb][lk + 5][lrow] = a1.y;
            As[nb][lk + 6][lrow] = a1.z; As[nb][lk + 7][lrow] = a1.w;
            Bs[nb][lk + 0][lrow] = b0.x; Bs[nb][lk + 1][lrow] = b0.y;
            Bs[nb][lk + 2][lrow] = b0.z; Bs[nb][lk + 3][lrow] = b0.w;
            Bs[nb][lk + 4][lrow] = b1.x; Bs[nb][lk + 5][lrow] = b1.y;
            Bs[nb][lk + 6][lrow] = b1.z; Bs[nb][lk + 7][lrow] = b1.w;
            __syncthreads();
            buf ^= 1;
        }
    }

    if (!qkv_mode) {
#pragma unroll
        for (int mi = 0; mi < 4; mi++) {
            int r = r0 + wm * 64 + mi * 16 + fr;
#pragma unroll
            for (int ni = 0; ni < 4; ni++) {
                int c = c0 + wn * 32 + ni * 8 + fc * 2;
                *(float2*)(D + (size_t)r * DIMC + c) =
                    make_float2(acc[mi][ni][0], acc[mi][ni][1]);
                *(float2*)(D + (size_t)(r + 8) * DIMC + c) =
                    make_float2(acc[mi][ni][2], acc[mi][ni][3]);
            }
        }
    } else {
#pragma unroll
        for (int mi = 0; mi < 4; mi++) {
            int row = r0 + wm * 64 + mi * 16 + fr;
#pragma unroll
            for (int half = 0; half < 2; half++) {
                int rr = row + half * 8;
                int b = rr >> 11;
                int t = rr & 2047;
#pragma unroll
                for (int ni = 0; ni < 4; ni++) {
                    int cc = wn * 32 + ni * 8 + fc * 2;
                    int h = blockIdx.x * 2 + (cc >> 6);
                    int d = cc & 63;
                    size_t idx = (((size_t)(b * NHEAD + h) * TT + t) * HDIM) + d;
                    *(float2*)(D + idx) =
                        make_float2(acc[mi][ni][half * 2 + 0],
                                    acc[mi][ni][half * 2 + 1]);
                }
            }
        }
    }
}

// ---------------------------------------------------------------------------
// Flash attention, tensor-core, full-row warps, BQ=128 (R9 structure) but
// now 2 CTAs/SM: __launch_bounds__(256,2) caps regs at 128, and the launch
// sets carveout=100% so 2 x 102KB smem co-resident -> 16 warps/SM.
// ---------------------------------------------------------------------------
#define ASTRIDE 68

__global__ __launch_bounds__(256, 2) void attn_kernel()
{
    extern __shared__ unsigned smu[];
    unsigned* Qs = smu;                    // [128][68] tf32, scaled by 0.125*log2e
    unsigned* Ks = Qs + 128 * ASTRIDE;     // [64][68]  tf32, [key][d]
    unsigned* Vt = Ks + 64 * ASTRIDE;      // [64][68]  tf32, [d][key]
    unsigned* Ps = Vt + 64 * ASTRIDE;      // [128][68] tf32 probs (warp-private rows)

    const int tid  = threadIdx.x;
    const int lane = tid & 31;
    const int w    = tid >> 5;        // warp owns rows w*16 .. w*16+15
    const int fr   = lane >> 2;       // 0..7
    const int fc   = lane & 3;        // 0..3

    const int bh = blockIdx.y;
    const int q0 = (gridDim.x - 1 - blockIdx.x) * 128;   // heavy tiles first

    const float* Q = g_q + (size_t)bh * TT * HDIM;
    const float* K = g_k + (size_t)bh * TT * HDIM;
    const float* V = g_v + (size_t)bh * TT * HDIM;

    const float qsc = 0.125f * 1.4426950408889634f;  // scale * log2(e)

    // Stage Q (tf32, scaled): 128 x 64
#pragma unroll
    for (int it = 0; it < 8; it++) {
        int e = tid + it * 256;
        int r = e >> 4, dq = (e & 15) * 4;
        float4 v4 = *(const float4*)(Q + (size_t)(q0 + r) * HDIM + dq);
        unsigned* p = &Qs[r * ASTRIDE + dq];
        p[0] = f2tf32(v4.x * qsc); p[1] = f2tf32(v4.y * qsc);
        p[2] = f2tf32(v4.z * qsc); p[3] = f2tf32(v4.w * qsc);
    }

    float O[8][4];
#pragma unroll
    for (int ni = 0; ni < 8; ni++)
#pragma unroll
        for (int e = 0; e < 4; e++) O[ni][e] = 0.f;
    float m_i[2] = {-1e30f, -1e30f};
    float l_i[2] = {0.f, 0.f};

    const int rbase = w * 16 + fr;
    const int ntiles = (q0 >> 6) + 2;

    for (int kt = 0; kt < ntiles; kt++) {
        const int k0 = kt * 64;
        __syncthreads();

        // Stage K: Ks[key][d]
#pragma unroll
        for (int it = 0; it < 4; it++) {
            int e = tid + it * 256;
            int k = e >> 4, dq = (e & 15) * 4;
            float4 kv = *(const float4*)(K + (size_t)(k0 + k) * HDIM + dq);
            unsigned* p = &Ks[k * ASTRIDE + dq];
            p[0] = f2tf32(kv.x); p[1] = f2tf32(kv.y);
            p[2] = f2tf32(kv.z); p[3] = f2tf32(kv.w);
        }
        // Stage V transposed: Vt[d][key]
#pragma unroll
        for (int it = 0; it < 4; it++) {
            int e = tid + it * 256;
            int d = e & 63;
            int kq = (e >> 6) * 4;
            float v0 = V[(size_t)(k0 + kq + 0) * HDIM + d];
            float v1 = V[(size_t)(k0 + kq + 1) * HDIM + d];
            float v2 = V[(size_t)(k0 + kq + 2) * HDIM + d];
            float v3 = V[(size_t)(k0 + kq + 3) * HDIM + d];
            *(uint4*)&Vt[d * ASTRIDE + kq] =
                make_uint4(f2tf32(v0), f2tf32(v1), f2tf32(v2), f2tf32(v3));
        }
        __syncthreads();

        // S = Qs @ Ks^T : warp computes 16 rows x 64 cols
        float sacc[8][4];
#pragma unroll
        for (int ni = 0; ni < 8; ni++)
#pragma unroll
            for (int e = 0; e < 4; e++) sacc[ni][e] = 0.f;

#pragma unroll
        for (int kk = 0; kk < 8; kk++) {
            unsigned af[4];
            {
                const unsigned* b = &Qs[rbase * ASTRIDE + kk * 8 + fc];
                af[0] = b[0];
                af[1] = b[8 * ASTRIDE];
                af[2] = b[4];
                af[3] = b[8 * ASTRIDE + 4];
            }
#pragma unroll
            for (int ni = 0; ni < 8; ni++) {
                const unsigned* b = &Ks[(ni * 8 + fr) * ASTRIDE + kk * 8 + fc];
                unsigned bf[2] = {b[0], b[4]};
                MMA_TF32(sacc[ni], af, bf);
            }
        }

        // Warp-local softmax (log2 domain)
        const bool need_mask = (k0 + 63 > q0);
#pragma unroll
        for (int h = 0; h < 2; h++) {
            const int rg = q0 + rbase + h * 8;
            float rm = -1e30f;
#pragma unroll
            for (int ni = 0; ni < 8; ni++)
#pragma unroll
            for (int e = 0; e < 2; e++) {
                float s = sacc[ni][h * 2 + e];
                if (need_mask && (k0 + ni * 8 + fc * 2 + e > rg)) s = -1e30f;
                sacc[ni][h * 2 + e] = s;
                rm = fmaxf(rm, s);
            }
            rm = fmaxf(rm, __shfl_xor_sync(0xffffffffu, rm, 1));
            rm = fmaxf(rm, __shfl_xor_sync(0xffffffffu, rm, 2));
            float mnew = fmaxf(m_i[h], rm);
            float al = exp2_fast(m_i[h] - mnew);
            m_i[h] = mnew;
            float rs = 0.f;
#pragma unroll
            for (int ni = 0; ni < 8; ni++) {
                float p0 = exp2_fast(sacc[ni][h * 2 + 0] - mnew);
                float p1 = exp2_fast(sacc[ni][h * 2 + 1] - mnew);
                rs += p0 + p1;
                *(uint2*)&Ps[(rbase + h * 8) * ASTRIDE + ni * 8 + fc * 2] =
                    make_uint2(f2tf32(p0), f2tf32(p1));
            }
            rs += __shfl_xor_sync(0xffffffffu, rs, 1);
            rs += __shfl_xor_sync(0xffffffffu, rs, 2);
            l_i[h] = l_i[h] * al + rs;
#pragma unroll
            for (int ni = 0; ni < 8; ni++) {
                O[ni][h * 2 + 0] *= al;
                O[ni][h * 2 + 1] *= al;
            }
        }
        __syncwarp();

        // O += P @ V
#pragma unroll
        for (int kk = 0; kk < 8; kk++) {
            unsigned af[4];
            {
                const unsigned* b = &Ps[rbase * ASTRIDE + kk * 8 + fc];
                af[0] = b[0];
                af[1] = b[8 * ASTRIDE];
                af[2] = b[4];
                af[3] = b[8 * ASTRIDE + 4];
            }
#pragma unroll
            for (int ni = 0; ni < 8; ni++) {
                const unsigned* b = &Vt[(ni * 8 + fr) * ASTRIDE + kk * 8 + fc];
                unsigned bf[2] = {b[0], b[4]};
                MMA_TF32(O[ni], af, bf);
            }
        }
    }

    // Epilogue: normalize, store tf32-rounded bits to [B*T, C]
    const int b = bh >> 4;
    const int h = bh & 15;
#pragma unroll
    for (int hh = 0; hh < 2; hh++) {
        float linv = 1.0f / l_i[hh];
        int row = q0 + rbase + hh * 8;
        unsigned* op = (unsigned*)g_att + ((size_t)(b * TT) + row) * DIMC + h * HDIM;
#pragma unroll
        for (int ni = 0; ni < 8; ni++) {
            *(uint2*)(op + ni * 8 + fc * 2) =
                make_uint2(f2tf32(O[ni][hh * 2 + 0] * linv),
                           f2tf32(O[ni][hh * 2 + 1] * linv));
        }
    }
}

#define ATTN_SMEM_BYTES ((128*ASTRIDE + 64*ASTRIDE + 64*ASTRIDE + 128*ASTRIDE) * 4)

// ---------------------------------------------------------------------------
extern "C" void kernel_launch(void* const* d_in, const int* in_sizes, int n_in,
                              void* d_out, int out_size)
{
    const float* x  = (const float*)d_in[0];
    // d_in[1] = mask (unused; causal applied analytically)
    const float* wq = (const float*)d_in[2];
    const float* wk = (const float*)d_in[3];
    const float* wv = (const float*)d_in[4];
    const float* wo = (const float*)d_in[5];
    float* out = (float*)d_out;

    float *dq, *dk, *dv, *datt;
    unsigned *dxc, *dwc;
    cudaGetSymbolAddress((void**)&dq,   g_q);
    cudaGetSymbolAddress((void**)&dk,   g_k);
    cudaGetSymbolAddress((void**)&dv,   g_v);
    cudaGetSymbolAddress((void**)&datt, g_att);
    cudaGetSymbolAddress((void**)&dxc,  g_xc);
    cudaGetSymbolAddress((void**)&dwc,  g_wc);

    cudaFuncSetAttribute(attn_kernel,
                         cudaFuncAttributeMaxDynamicSharedMemorySize,
                         ATTN_SMEM_BYTES);
    cudaFuncSetAttribute(attn_kernel,
                         cudaFuncAttributePreferredSharedMemoryCarveout, 100);

    // Prepass: round x + weights to tf32
    conv_in_kernel<<<(XF4 + 4 * WF4) / 256, 256>>>(x, wq, wk, wv, wo);

    // QKV projections: 128x128 tiles, grid (8, 64, 3)
    gemm_kernel<<<dim3(8, 64, 3), 256>>>(
        dxc, dwc, dwc + DIMC * DIMC, dwc + 2 * DIMC * DIMC,
        dq, dk, dv, 1);

    // Flash attention: grid (16 q-tiles of 128, 64 b*h)
    attn_kernel<<<dim3(16, 64), 256, ATTN_SMEM_BYTES>>>();

    // Output projection (g_att already holds tf32 bits)
    gemm_kernel<<<dim3(8, 64, 1), 256>>>(
        (unsigned*)datt, dwc + 3 * DIMC * DIMC, nullptr, nullptr,
        out, nullptr, nullptr, 0);
}

// round 13
// speedup vs baseline: 1.2954x; 1.2318x over previous
#include <cuda_runtime.h>
#include <cuda_bf16.h>
#include <cstdint>

#define DIMC 1024
#define NHEAD 16
#define HDIM 64
#define BB 4
#define TT 2048
#define MROWS (BB * TT)   // 8192

// Scratch (device globals — allocation-free contract)
__device__ float g_q[BB * NHEAD * TT * HDIM];   // [B,H,T,D]
__device__ float g_k[BB * NHEAD * TT * HDIM];
__device__ float g_v[BB * NHEAD * TT * HDIM];
__device__ float g_att[MROWS * DIMC];           // [B*T, C] attn out (tf32 bits)
__device__ unsigned g_xc[MROWS * DIMC];         // tf32-rounded x
__device__ unsigned g_wc[4 * DIMC * DIMC];      // tf32-rounded wq|wk|wv|wo

__device__ __forceinline__ unsigned f2tf32(float x) {
    unsigned u;
    asm("cvt.rna.tf32.f32 %0, %1;" : "=r"(u) : "f"(x));
    return u;
}

// 2^x on the FMA/ALU pipes (no MUFU). x <= 0 expected; clamped at -120.
__device__ __forceinline__ float exp2_fast(float x) {
    x = fmaxf(x, -120.f);
    float n = floorf(x);
    float f = x - n;                 // [0,1)
    float p = 1.78656e-4f;
    p = fmaf(p, f, 1.33336e-3f);
    p = fmaf(p, f, 9.61813e-3f);
    p = fmaf(p, f, 5.55041e-2f);
    p = fmaf(p, f, 2.40226507e-1f);
    p = fmaf(p, f, 6.93147181e-1f);
    p = fmaf(p, f, 1.0f);
    return __uint_as_float(__float_as_uint(p) + (((int)n) << 23));
}

#define MMA_TF32(d, a, b)                                                    \
    asm volatile("mma.sync.aligned.m16n8k8.row.col.f32.tf32.tf32.f32 "        \
                 "{%0,%1,%2,%3}, {%4,%5,%6,%7}, {%8,%9}, {%0,%1,%2,%3};"      \
                 : "+f"(d[0]), "+f"(d[1]), "+f"(d[2]), "+f"(d[3])             \
                 : "r"(a[0]), "r"(a[1]), "r"(a[2]), "r"(a[3]),                \
                   "r"(b[0]), "r"(b[1]))

// ---------------------------------------------------------------------------
// Prepass: tf32-round x and the four weights into unsigned scratch.
// ---------------------------------------------------------------------------
#define XF4  (MROWS * DIMC / 4)
#define WF4  (DIMC * DIMC / 4)

__global__ __launch_bounds__(256) void conv_in_kernel(
    const float* __restrict__ x,
    const float* __restrict__ wq, const float* __restrict__ wk,
    const float* __restrict__ wv, const float* __restrict__ wo)
{
    int i = blockIdx.x * 256 + threadIdx.x;
    const float* src;
    unsigned* dst;
    int off;
    if (i < XF4) { src = x; dst = g_xc; off = i; }
    else {
        int j = i - XF4;
        int seg = j >> 18;
        off = j & (WF4 - 1);
        src = seg == 0 ? wq : seg == 1 ? wk : seg == 2 ? wv : wo;
        dst = g_wc + seg * (DIMC * DIMC);
    }
    float4 v = *(const float4*)(src + (size_t)off * 4);
    *(uint4*)(dst + (size_t)off * 4) =
        make_uint4(f2tf32(v.x), f2tf32(v.y), f2tf32(v.z), f2tf32(v.w));
}

// ---------------------------------------------------------------------------
// TF32 mma.sync GEMM with cp.async 4-stage pipeline.
// C[M,N] = A[M,K] @ W[N,K]^T, inputs pre-rounded tf32.
// 128x128 block, 16-k per stage, 256 threads (8 warps, 2x4, 64x32/warp).
// Smem: per stage A[128 rows][20 words] + B[128][20] (row-padded: banks
// 20r mod 32 covers all 8 groups; cp.async dst 16B-aligned since 80=5*16).
// One __syncthreads per stage; cp.async 3 stages ahead.
// ---------------------------------------------------------------------------
#define ROWW 20                         // words per row (16 data + 4 pad)
#define STG_WORDS (128 * ROWW * 2)      // A + B per stage = 5120 words
#define NSTAGE_TOTAL (DIMC / 16)        // 64
#define GSM_BYTES (4 * STG_WORDS * 4)   // 81920

__device__ __forceinline__ void stage_copy(
    const unsigned* __restrict__ A, const unsigned* __restrict__ W,
    int r0, int c0, uint32_t sb, int tid, int c)
{
    uint32_t base = sb + (uint32_t)(c & 3) * (STG_WORDS * 4);
#pragma unroll
    for (int j = 0; j < 2; j++) {
        int q = tid + j * 256;          // 0..511
        int row = q >> 2, kc = q & 3;
        const unsigned* srca = A + (size_t)(r0 + row) * DIMC + c * 16 + kc * 4;
        uint32_t dst = base + row * (ROWW * 4) + kc * 16;
        asm volatile("cp.async.cg.shared.global [%0], [%1], 16;"
                     :: "r"(dst), "l"(srca) : "memory");
        const unsigned* srcb = W + (size_t)(c0 + row) * DIMC + c * 16 + kc * 4;
        asm volatile("cp.async.cg.shared.global [%0], [%1], 16;"
                     :: "r"(dst + 128 * ROWW * 4), "l"(srcb) : "memory");
    }
}

__device__ __forceinline__ uint32_t smem_u32(const void* p) {
    uint32_t a;
    asm("{ .reg .u64 t; cvta.to.shared.u64 t, %1; cvt.u32.u64 %0, t; }"
        : "=r"(a) : "l"(p));
    return a;
}

__global__ __launch_bounds__(256, 2) void gemm_kernel(
    const unsigned* __restrict__ A,
    const unsigned* __restrict__ W0, const unsigned* __restrict__ W1,
    const unsigned* __restrict__ W2,
    float* __restrict__ D0, float* __restrict__ D1, float* __restrict__ D2,
    int qkv_mode)
{
    extern __shared__ unsigned smg[];
    const uint32_t sb = smem_u32(smg);

    const unsigned* W = W0;
    float* D = D0;
    if (blockIdx.z == 1) { W = W1; D = D1; }
    else if (blockIdx.z == 2) { W = W2; D = D2; }

    const int tid  = threadIdx.x;
    const int lane = tid & 31;
    const int w    = tid >> 5;
    const int wm   = w >> 2;          // 0..1
    const int wn   = w & 3;           // 0..3
    const int r0 = blockIdx.y * 128;
    const int c0 = blockIdx.x * 128;

    const int fr = lane >> 2;            // 0..7
    const int fc = lane & 3;             // 0..3

    float acc[4][4][4];
#pragma unroll
    for (int mi = 0; mi < 4; mi++)
#pragma unroll
        for (int ni = 0; ni < 4; ni++)
#pragma unroll
            for (int e = 0; e < 4; e++) acc[mi][ni][e] = 0.f;

    // prologue: prefetch stages 0..2
    stage_copy(A, W, r0, c0, sb, tid, 0);
    asm volatile("cp.async.commit_group;" ::: "memory");
    stage_copy(A, W, r0, c0, sb, tid, 1);
    asm volatile("cp.async.commit_group;" ::: "memory");
    stage_copy(A, W, r0, c0, sb, tid, 2);
    asm volatile("cp.async.commit_group;" ::: "memory");

    for (int c = 0; c < NSTAGE_TOTAL; c++) {
        asm volatile("cp.async.wait_group 2;" ::: "memory");
        __syncthreads();

        const unsigned* Ab = smg + (size_t)(c & 3) * STG_WORDS;
        const unsigned* Bb = Ab + 128 * ROWW;

#pragma unroll
        for (int kk = 0; kk < 2; kk++) {
            unsigned af[4][4], bfr[4][2];
#pragma unroll
            for (int mi = 0; mi < 4; mi++) {
                int row = wm * 64 + mi * 16 + fr;
                const unsigned* p0 = Ab + row * ROWW + kk * 8 + fc;
                af[mi][0] = p0[0];
                af[mi][1] = p0[8 * ROWW];
                af[mi][2] = p0[4];
                af[mi][3] = p0[8 * ROWW + 4];
            }
#pragma unroll
            for (int ni = 0; ni < 4; ni++) {
                int col = wn * 32 + ni * 8 + fr;
                const unsigned* p0 = Bb + col * ROWW + kk * 8 + fc;
                bfr[ni][0] = p0[0];
                bfr[ni][1] = p0[4];
            }
#pragma unroll
            for (int mi = 0; mi < 4; mi++)
#pragma unroll
                for (int ni = 0; ni < 4; ni++)
                    MMA_TF32(acc[mi][ni], af[mi], bfr[ni]);
        }

        if (c + 3 < NSTAGE_TOTAL)
            stage_copy(A, W, r0, c0, sb, tid, c + 3);
        asm volatile("cp.async.commit_group;" ::: "memory");
    }

    // epilogue
    if (!qkv_mode) {
#pragma unroll
        for (int mi = 0; mi < 4; mi++) {
            int r = r0 + wm * 64 + mi * 16 + fr;
#pragma unroll
            for (int ni = 0; ni < 4; ni++) {
                int c = c0 + wn * 32 + ni * 8 + fc * 2;
                *(float2*)(D + (size_t)r * DIMC + c) =
                    make_float2(acc[mi][ni][0], acc[mi][ni][1]);
                *(float2*)(D + (size_t)(r + 8) * DIMC + c) =
                    make_float2(acc[mi][ni][2], acc[mi][ni][3]);
            }
        }
    } else {
#pragma unroll
        for (int mi = 0; mi < 4; mi++) {
            int row = r0 + wm * 64 + mi * 16 + fr;
#pragma unroll
            for (int half = 0; half < 2; half++) {
                int rr = row + half * 8;
                int b = rr >> 11;
                int t = rr & 2047;
#pragma unroll
                for (int ni = 0; ni < 4; ni++) {
                    int cc = wn * 32 + ni * 8 + fc * 2;
                    int h = blockIdx.x * 2 + (cc >> 6);
                    int d = cc & 63;
                    size_t idx = (((size_t)(b * NHEAD + h) * TT + t) * HDIM) + d;
                    *(float2*)(D + idx) =
                        make_float2(acc[mi][ni][half * 2 + 0],
                                    acc[mi][ni][half * 2 + 1]);
                }
            }
        }
    }
}

// ---------------------------------------------------------------------------
// Flash attention (unchanged from R11): tensor-core mma.sync, full-row warps,
// BQ=128, 2 CTAs/SM. Epilogue stores tf32 bits into g_att.
// ---------------------------------------------------------------------------
#define ASTRIDE 68

__global__ __launch_bounds__(256, 2) void attn_kernel()
{
    extern __shared__ unsigned smu[];
    unsigned* Qs = smu;
    unsigned* Ks = Qs + 128 * ASTRIDE;
    unsigned* Vt = Ks + 64 * ASTRIDE;
    unsigned* Ps = Vt + 64 * ASTRIDE;

    const int tid  = threadIdx.x;
    const int lane = tid & 31;
    const int w    = tid >> 5;
    const int fr   = lane >> 2;
    const int fc   = lane & 3;

    const int bh = blockIdx.y;
    const int q0 = (gridDim.x - 1 - blockIdx.x) * 128;

    const float* Q = g_q + (size_t)bh * TT * HDIM;
    const float* K = g_k + (size_t)bh * TT * HDIM;
    const float* V = g_v + (size_t)bh * TT * HDIM;

    const float qsc = 0.125f * 1.4426950408889634f;

#pragma unroll
    for (int it = 0; it < 8; it++) {
        int e = tid + it * 256;
        int r = e >> 4, dq = (e & 15) * 4;
        float4 v4 = *(const float4*)(Q + (size_t)(q0 + r) * HDIM + dq);
        unsigned* p = &Qs[r * ASTRIDE + dq];
        p[0] = f2tf32(v4.x * qsc); p[1] = f2tf32(v4.y * qsc);
        p[2] = f2tf32(v4.z * qsc); p[3] = f2tf32(v4.w * qsc);
    }

    float O[8][4];
#pragma unroll
    for (int ni = 0; ni < 8; ni++)
#pragma unroll
        for (int e = 0; e < 4; e++) O[ni][e] = 0.f;
    float m_i[2] = {-1e30f, -1e30f};
    float l_i[2] = {0.f, 0.f};

    const int rbase = w * 16 + fr;
    const int ntiles = (q0 >> 6) + 2;

    for (int kt = 0; kt < ntiles; kt++) {
        const int k0 = kt * 64;
        __syncthreads();

#pragma unroll
        for (int it = 0; it < 4; it++) {
            int e = tid + it * 256;
            int k = e >> 4, dq = (e & 15) * 4;
            float4 kv = *(const float4*)(K + (size_t)(k0 + k) * HDIM + dq);
            unsigned* p = &Ks[k * ASTRIDE + dq];
            p[0] = f2tf32(kv.x); p[1] = f2tf32(kv.y);
            p[2] = f2tf32(kv.z); p[3] = f2tf32(kv.w);
        }
#pragma unroll
        for (int it = 0; it < 4; it++) {
            int e = tid + it * 256;
            int d = e & 63;
            int kq = (e >> 6) * 4;
            float v0 = V[(size_t)(k0 + kq + 0) * HDIM + d];
            float v1 = V[(size_t)(k0 + kq + 1) * HDIM + d];
            float v2 = V[(size_t)(k0 + kq + 2) * HDIM + d];
            float v3 = V[(size_t)(k0 + kq + 3) * HDIM + d];
            *(uint4*)&Vt[d * ASTRIDE + kq] =
                make_uint4(f2tf32(v0), f2tf32(v1), f2tf32(v2), f2tf32(v3));
        }
        __syncthreads();

        float sacc[8][4];
#pragma unroll
        for (int ni = 0; ni < 8; ni++)
#pragma unroll
            for (int e = 0; e < 4; e++) sacc[ni][e] = 0.f;

#pragma unroll
        for (int kk = 0; kk < 8; kk++) {
            unsigned af[4];
            {
                const unsigned* b = &Qs[rbase * ASTRIDE + kk * 8 + fc];
                af[0] = b[0];
                af[1] = b[8 * ASTRIDE];
                af[2] = b[4];
                af[3] = b[8 * ASTRIDE + 4];
            }
#pragma unroll
            for (int ni = 0; ni < 8; ni++) {
                const unsigned* b = &Ks[(ni * 8 + fr) * ASTRIDE + kk * 8 + fc];
                unsigned bf[2] = {b[0], b[4]};
                MMA_TF32(sacc[ni], af, bf);
            }
        }

        const bool need_mask = (k0 + 63 > q0);
#pragma unroll
        for (int h = 0; h < 2; h++) {
            const int rg = q0 + rbase + h * 8;
            float rm = -1e30f;
#pragma unroll
            for (int ni = 0; ni < 8; ni++)
#pragma unroll
            for (int e = 0; e < 2; e++) {
                float s = sacc[ni][h * 2 + e];
                if (need_mask && (k0 + ni * 8 + fc * 2 + e > rg)) s = -1e30f;
                sacc[ni][h * 2 + e] = s;
                rm = fmaxf(rm, s);
            }
            rm = fmaxf(rm, __shfl_xor_sync(0xffffffffu, rm, 1));
            rm = fmaxf(rm, __shfl_xor_sync(0xffffffffu, rm, 2));
            float mnew = fmaxf(m_i[h], rm);
            float al = exp2_fast(m_i[h] - mnew);
            m_i[h] = mnew;
            float rs = 0.f;
#pragma unroll
            for (int ni = 0; ni < 8; ni++) {
                float p0 = exp2_fast(sacc[ni][h * 2 + 0] - mnew);
                float p1 = exp2_fast(sacc[ni][h * 2 + 1] - mnew);
                rs += p0 + p1;
                *(uint2*)&Ps[(rbase + h * 8) * ASTRIDE + ni * 8 + fc * 2] =
                    make_uint2(f2tf32(p0), f2tf32(p1));
            }
            rs += __shfl_xor_sync(0xffffffffu, rs, 1);
            rs += __shfl_xor_sync(0xffffffffu, rs, 2);
            l_i[h] = l_i[h] * al + rs;
#pragma unroll
            for (int ni = 0; ni < 8; ni++) {
                O[ni][h * 2 + 0] *= al;
                O[ni][h * 2 + 1] *= al;
            }
        }
        __syncwarp();

#pragma unroll
        for (int kk = 0; kk < 8; kk++) {
            unsigned af[4];
            {
                const unsigned* b = &Ps[rbase * ASTRIDE + kk * 8 + fc];
                af[0] = b[0];
                af[1] = b[8 * ASTRIDE];
                af[2] = b[4];
                af[3] = b[8 * ASTRIDE + 4];
            }
#pragma unroll
            for (int ni = 0; ni < 8; ni++) {
                const unsigned* b = &Vt[(ni * 8 + fr) * ASTRIDE + kk * 8 + fc];
                unsigned bf[2] = {b[0], b[4]};
                MMA_TF32(O[ni], af, bf);
            }
        }
    }

    const int b = bh >> 4;
    const int h = bh & 15;
#pragma unroll
    for (int hh = 0; hh < 2; hh++) {
        float linv = 1.0f / l_i[hh];
        int row = q0 + rbase + hh * 8;
        unsigned* op = (unsigned*)g_att + ((size_t)(b * TT) + row) * DIMC + h * HDIM;
#pragma unroll
        for (int ni = 0; ni < 8; ni++) {
            *(uint2*)(op + ni * 8 + fc * 2) =
                make_uint2(f2tf32(O[ni][hh * 2 + 0] * linv),
                           f2tf32(O[ni][hh * 2 + 1] * linv));
        }
    }
}

#define ATTN_SMEM_BYTES ((128*ASTRIDE + 64*ASTRIDE + 64*ASTRIDE + 128*ASTRIDE) * 4)

// ---------------------------------------------------------------------------
extern "C" void kernel_launch(void* const* d_in, const int* in_sizes, int n_in,
                              void* d_out, int out_size)
{
    const float* x  = (const float*)d_in[0];
    // d_in[1] = mask (unused; causal applied analytically)
    const float* wq = (const float*)d_in[2];
    const float* wk = (const float*)d_in[3];
    const float* wv = (const float*)d_in[4];
    const float* wo = (const float*)d_in[5];
    float* out = (float*)d_out;

    float *dq, *dk, *dv, *datt;
    unsigned *dxc, *dwc;
    cudaGetSymbolAddress((void**)&dq,   g_q);
    cudaGetSymbolAddress((void**)&dk,   g_k);
    cudaGetSymbolAddress((void**)&dv,   g_v);
    cudaGetSymbolAddress((void**)&datt, g_att);
    cudaGetSymbolAddress((void**)&dxc,  g_xc);
    cudaGetSymbolAddress((void**)&dwc,  g_wc);

    cudaFuncSetAttribute(attn_kernel,
                         cudaFuncAttributeMaxDynamicSharedMemorySize,
                         ATTN_SMEM_BYTES);
    cudaFuncSetAttribute(attn_kernel,
                         cudaFuncAttributePreferredSharedMemoryCarveout, 100);
    cudaFuncSetAttribute(gemm_kernel,
                         cudaFuncAttributeMaxDynamicSharedMemorySize,
                         GSM_BYTES);
    cudaFuncSetAttribute(gemm_kernel,
                         cudaFuncAttributePreferredSharedMemoryCarveout, 100);

    // Prepass: round x + weights to tf32
    conv_in_kernel<<<(XF4 + 4 * WF4) / 256, 256>>>(x, wq, wk, wv, wo);

    // QKV projections: 128x128 tiles, grid (8, 64, 3)
    gemm_kernel<<<dim3(8, 64, 3), 256, GSM_BYTES>>>(
        dxc, dwc, dwc + DIMC * DIMC, dwc + 2 * DIMC * DIMC,
        dq, dk, dv, 1);

    // Flash attention: grid (16 q-tiles of 128, 64 b*h)
    attn_kernel<<<dim3(16, 64), 256, ATTN_SMEM_BYTES>>>();

    // Output projection (g_att already holds tf32 bits)
    gemm_kernel<<<dim3(8, 64, 1), 256, GSM_BYTES>>>(
        (unsigned*)datt, dwc + 3 * DIMC * DIMC, nullptr, nullptr,
        out, nullptr, nullptr, 0);
}

// round 14
// speedup vs baseline: 1.3591x; 1.0491x over previous
#include <cuda_runtime.h>
#include <cuda_bf16.h>
#include <cstdint>

#define DIMC 1024
#define NHEAD 16
#define HDIM 64
#define BB 4
#define TT 2048
#define MROWS (BB * TT)   // 8192

// Scratch (device globals — allocation-free contract)
__device__ float g_q[BB * NHEAD * TT * HDIM];   // [B,H,T,D]  tf32 bits (pre-scaled)
__device__ float g_k[BB * NHEAD * TT * HDIM];   // [B,H,T,D]  tf32 bits
__device__ float g_vt[BB * NHEAD * HDIM * TT];  // [B,H,D,T]  tf32 bits (transposed)
__device__ float g_att[MROWS * DIMC];           // [B*T, C]   tf32 bits
__device__ unsigned g_xc[MROWS * DIMC];         // tf32-rounded x
__device__ unsigned g_wc[4 * DIMC * DIMC];      // tf32-rounded wq*qsc|wk|wv|wo

__device__ __forceinline__ unsigned f2tf32(float x) {
    unsigned u;
    asm("cvt.rna.tf32.f32 %0, %1;" : "=r"(u) : "f"(x));
    return u;
}

// 2^x on the FMA/ALU pipes (no MUFU). x <= 0 expected; clamped at -120.
__device__ __forceinline__ float exp2_fast(float x) {
    x = fmaxf(x, -120.f);
    float n = floorf(x);
    float f = x - n;
    float p = 1.78656e-4f;
    p = fmaf(p, f, 1.33336e-3f);
    p = fmaf(p, f, 9.61813e-3f);
    p = fmaf(p, f, 5.55041e-2f);
    p = fmaf(p, f, 2.40226507e-1f);
    p = fmaf(p, f, 6.93147181e-1f);
    p = fmaf(p, f, 1.0f);
    return __uint_as_float(__float_as_uint(p) + (((int)n) << 23));
}

#define MMA_TF32(d, a, b)                                                    \
    asm volatile("mma.sync.aligned.m16n8k8.row.col.f32.tf32.tf32.f32 "        \
                 "{%0,%1,%2,%3}, {%4,%5,%6,%7}, {%8,%9}, {%0,%1,%2,%3};"      \
                 : "+f"(d[0]), "+f"(d[1]), "+f"(d[2]), "+f"(d[3])             \
                 : "r"(a[0]), "r"(a[1]), "r"(a[2]), "r"(a[3]),                \
                   "r"(b[0]), "r"(b[1]))

__device__ __forceinline__ uint32_t smem_u32(const void* p) {
    uint32_t a;
    asm("{ .reg .u64 t; cvta.to.shared.u64 t, %1; cvt.u32.u64 %0, t; }"
        : "=r"(a) : "l"(p));
    return a;
}

// ---------------------------------------------------------------------------
// Prepass: tf32-round x and weights; wq is pre-scaled by 0.125*log2(e).
// ---------------------------------------------------------------------------
#define XF4  (MROWS * DIMC / 4)
#define WF4  (DIMC * DIMC / 4)

__global__ __launch_bounds__(256) void conv_in_kernel(
    const float* __restrict__ x,
    const float* __restrict__ wq, const float* __restrict__ wk,
    const float* __restrict__ wv, const float* __restrict__ wo)
{
    int i = blockIdx.x * 256 + threadIdx.x;
    const float* src;
    unsigned* dst;
    int off;
    float sc = 1.0f;
    if (i < XF4) { src = x; dst = g_xc; off = i; }
    else {
        int j = i - XF4;
        int seg = j >> 18;
        off = j & (WF4 - 1);
        src = seg == 0 ? wq : seg == 1 ? wk : seg == 2 ? wv : wo;
        dst = g_wc + seg * (DIMC * DIMC);
        if (seg == 0) sc = 0.125f * 1.4426950408889634f;
    }
    float4 v = *(const float4*)(src + (size_t)off * 4);
    *(uint4*)(dst + (size_t)off * 4) =
        make_uint4(f2tf32(v.x * sc), f2tf32(v.y * sc),
                   f2tf32(v.z * sc), f2tf32(v.w * sc));
}

// ---------------------------------------------------------------------------
// TF32 mma.sync GEMM with cp.async 4-stage pipeline (R13 core).
// qkv_mode=1: store tf32 bits; Q/K natural [B,H,T,D], V transposed [B,H,D,T].
// ---------------------------------------------------------------------------
#define ROWW 20
#define STG_WORDS (128 * ROWW * 2)
#define NSTAGE_TOTAL (DIMC / 16)
#define GSM_BYTES (4 * STG_WORDS * 4)

__device__ __forceinline__ void stage_copy(
    const unsigned* __restrict__ A, const unsigned* __restrict__ W,
    int r0, int c0, uint32_t sb, int tid, int c)
{
    uint32_t base = sb + (uint32_t)(c & 3) * (STG_WORDS * 4);
#pragma unroll
    for (int j = 0; j < 2; j++) {
        int q = tid + j * 256;
        int row = q >> 2, kc = q & 3;
        const unsigned* srca = A + (size_t)(r0 + row) * DIMC + c * 16 + kc * 4;
        uint32_t dst = base + row * (ROWW * 4) + kc * 16;
        asm volatile("cp.async.cg.shared.global [%0], [%1], 16;"
                     :: "r"(dst), "l"(srca) : "memory");
        const unsigned* srcb = W + (size_t)(c0 + row) * DIMC + c * 16 + kc * 4;
        asm volatile("cp.async.cg.shared.global [%0], [%1], 16;"
                     :: "r"(dst + 128 * ROWW * 4), "l"(srcb) : "memory");
    }
}

__global__ __launch_bounds__(256, 2) void gemm_kernel(
    const unsigned* __restrict__ A,
    const unsigned* __restrict__ W0, const unsigned* __restrict__ W1,
    const unsigned* __restrict__ W2,
    float* __restrict__ D0, float* __restrict__ D1, float* __restrict__ D2,
    int qkv_mode)
{
    extern __shared__ unsigned smg[];
    const uint32_t sb = smem_u32(smg);

    const unsigned* W = W0;
    float* D = D0;
    if (blockIdx.z == 1) { W = W1; D = D1; }
    else if (blockIdx.z == 2) { W = W2; D = D2; }

    const int tid  = threadIdx.x;
    const int lane = tid & 31;
    const int w    = tid >> 5;
    const int wm   = w >> 2;
    const int wn   = w & 3;
    const int r0 = blockIdx.y * 128;
    const int c0 = blockIdx.x * 128;

    const int fr = lane >> 2;
    const int fc = lane & 3;

    float acc[4][4][4];
#pragma unroll
    for (int mi = 0; mi < 4; mi++)
#pragma unroll
        for (int ni = 0; ni < 4; ni++)
#pragma unroll
            for (int e = 0; e < 4; e++) acc[mi][ni][e] = 0.f;

    stage_copy(A, W, r0, c0, sb, tid, 0);
    asm volatile("cp.async.commit_group;" ::: "memory");
    stage_copy(A, W, r0, c0, sb, tid, 1);
    asm volatile("cp.async.commit_group;" ::: "memory");
    stage_copy(A, W, r0, c0, sb, tid, 2);
    asm volatile("cp.async.commit_group;" ::: "memory");

    for (int c = 0; c < NSTAGE_TOTAL; c++) {
        asm volatile("cp.async.wait_group 2;" ::: "memory");
        __syncthreads();

        const unsigned* Ab = smg + (size_t)(c & 3) * STG_WORDS;
        const unsigned* Bb = Ab + 128 * ROWW;

#pragma unroll
        for (int kk = 0; kk < 2; kk++) {
            unsigned af[4][4], bfr[4][2];
#pragma unroll
            for (int mi = 0; mi < 4; mi++) {
                int row = wm * 64 + mi * 16 + fr;
                const unsigned* p0 = Ab + row * ROWW + kk * 8 + fc;
                af[mi][0] = p0[0];
                af[mi][1] = p0[8 * ROWW];
                af[mi][2] = p0[4];
                af[mi][3] = p0[8 * ROWW + 4];
            }
#pragma unroll
            for (int ni = 0; ni < 4; ni++) {
                int col = wn * 32 + ni * 8 + fr;
                const unsigned* p0 = Bb + col * ROWW + kk * 8 + fc;
                bfr[ni][0] = p0[0];
                bfr[ni][1] = p0[4];
            }
#pragma unroll
            for (int mi = 0; mi < 4; mi++)
#pragma unroll
                for (int ni = 0; ni < 4; ni++)
                    MMA_TF32(acc[mi][ni], af[mi], bfr[ni]);
        }

        if (c + 3 < NSTAGE_TOTAL)
            stage_copy(A, W, r0, c0, sb, tid, c + 3);
        asm volatile("cp.async.commit_group;" ::: "memory");
    }

    if (!qkv_mode) {
#pragma unroll
        for (int mi = 0; mi < 4; mi++) {
            int r = r0 + wm * 64 + mi * 16 + fr;
#pragma unroll
            for (int ni = 0; ni < 4; ni++) {
                int c = c0 + wn * 32 + ni * 8 + fc * 2;
                *(float2*)(D + (size_t)r * DIMC + c) =
                    make_float2(acc[mi][ni][0], acc[mi][ni][1]);
                *(float2*)(D + (size_t)(r + 8) * DIMC + c) =
                    make_float2(acc[mi][ni][2], acc[mi][ni][3]);
            }
        }
    } else if (blockIdx.z != 2) {
        // Q/K: natural [B,H,T,D], tf32 bits
#pragma unroll
        for (int mi = 0; mi < 4; mi++) {
            int row = r0 + wm * 64 + mi * 16 + fr;
#pragma unroll
            for (int half = 0; half < 2; half++) {
                int rr = row + half * 8;
                int b = rr >> 11;
                int t = rr & 2047;
#pragma unroll
                for (int ni = 0; ni < 4; ni++) {
                    int cc = wn * 32 + ni * 8 + fc * 2;
                    int h = blockIdx.x * 2 + (cc >> 6);
                    int d = cc & 63;
                    size_t idx = (((size_t)(b * NHEAD + h) * TT + t) * HDIM) + d;
                    unsigned u0 = f2tf32(acc[mi][ni][half * 2 + 0]);
                    unsigned u1 = f2tf32(acc[mi][ni][half * 2 + 1]);
                    *(uint2*)((unsigned*)D + idx) = make_uint2(u0, u1);
                }
            }
        }
    } else {
        // V: transposed [B,H,D,T], tf32 bits
#pragma unroll
        for (int mi = 0; mi < 4; mi++) {
            int row = r0 + wm * 64 + mi * 16 + fr;
#pragma unroll
            for (int half = 0; half < 2; half++) {
                int rr = row + half * 8;
                int b = rr >> 11;
                int t = rr & 2047;
#pragma unroll
                for (int ni = 0; ni < 4; ni++) {
                    int cc = wn * 32 + ni * 8 + fc * 2;
                    int h = blockIdx.x * 2 + (cc >> 6);
                    int d = cc & 63;
                    size_t base = ((size_t)(b * NHEAD + h) * HDIM + d) * TT + t;
                    ((unsigned*)D)[base]      = f2tf32(acc[mi][ni][half * 2 + 0]);
                    ((unsigned*)D)[base + TT] = f2tf32(acc[mi][ni][half * 2 + 1]);
                }
            }
        }
    }
}

// ---------------------------------------------------------------------------
// Flash attention: Q fragments in registers; K/V double-buffered in smem via
// cp.async (all operands pre-rounded tf32, V pre-transposed). 1 barrier +
// 8 cp.async issues per thread per 64-key tile. BQ=128, 2 CTAs/SM.
// ---------------------------------------------------------------------------
#define ASTRIDE 68
#define KVW (64 * ASTRIDE)              // words per K or V tile
#define KVBUF (2 * KVW)                 // K+V per buffer
#define ATTN_SMEM_BYTES ((2 * KVBUF + 128 * ASTRIDE) * 4)   // 104448

__device__ __forceinline__ void stage_kv(
    const unsigned* __restrict__ Kg, const unsigned* __restrict__ Vg,
    uint32_t sb, int tid, int k0, int buf)
{
    uint32_t base = sb + (uint32_t)buf * (KVBUF * 4);
#pragma unroll
    for (int j = 0; j < 4; j++) {
        int u = tid + j * 256;          // 0..1023
        int row = u >> 4;               // 0..63
        int ch  = u & 15;               // 16B chunk
        const unsigned* sk = Kg + (size_t)(k0 + row) * HDIM + ch * 4;
        uint32_t dst = base + row * (ASTRIDE * 4) + ch * 16;
        asm volatile("cp.async.cg.shared.global [%0], [%1], 16;"
                     :: "r"(dst), "l"(sk) : "memory");
        const unsigned* sv = Vg + (size_t)row * TT + k0 + ch * 4;
        asm volatile("cp.async.cg.shared.global [%0], [%1], 16;"
                     :: "r"(dst + KVW * 4), "l"(sv) : "memory");
    }
}

__global__ __launch_bounds__(256, 2) void attn_kernel()
{
    extern __shared__ unsigned smu[];
    const uint32_t sb = smem_u32(smu);
    unsigned* Ps = smu + 2 * KVBUF;     // [128][68] tf32 probs (warp-private rows)

    const int tid  = threadIdx.x;
    const int lane = tid & 31;
    const int w    = tid >> 5;
    const int fr   = lane >> 2;
    const int fc   = lane & 3;

    const int bh = blockIdx.y;
    const int q0 = (gridDim.x - 1 - blockIdx.x) * 128;

    const unsigned* Qg = (const unsigned*)g_q + (size_t)bh * TT * HDIM;
    const unsigned* Kg = (const unsigned*)g_k + (size_t)bh * TT * HDIM;
    const unsigned* Vg = (const unsigned*)g_vt + (size_t)bh * HDIM * TT;

    const int rbase = w * 16 + fr;

    // Q fragments -> registers (rows rbase, rbase+8; one-time)
    unsigned aq[8][4];
    {
        const unsigned* q0p = Qg + (size_t)(q0 + rbase) * HDIM;
        const unsigned* q1p = q0p + 8 * HDIM;
#pragma unroll
        for (int kk = 0; kk < 8; kk++) {
            aq[kk][0] = q0p[kk * 8 + fc];
            aq[kk][1] = q1p[kk * 8 + fc];
            aq[kk][2] = q0p[kk * 8 + fc + 4];
            aq[kk][3] = q1p[kk * 8 + fc + 4];
        }
    }

    float O[8][4];
#pragma unroll
    for (int ni = 0; ni < 8; ni++)
#pragma unroll
        for (int e = 0; e < 4; e++) O[ni][e] = 0.f;
    float m_i[2] = {-1e30f, -1e30f};
    float l_i[2] = {0.f, 0.f};

    const int ntiles = (q0 >> 6) + 2;

    stage_kv(Kg, Vg, sb, tid, 0, 0);
    asm volatile("cp.async.commit_group;" ::: "memory");

    for (int kt = 0; kt < ntiles; kt++) {
        const int k0 = kt * 64;
        asm volatile("cp.async.wait_group 0;" ::: "memory");
        __syncthreads();

        if (kt + 1 < ntiles) {
            stage_kv(Kg, Vg, sb, tid, k0 + 64, (kt + 1) & 1);
            asm volatile("cp.async.commit_group;" ::: "memory");
        }

        const unsigned* Kb = smu + (size_t)(kt & 1) * KVBUF;
        const unsigned* Vb = Kb + KVW;

        // S = Q @ K^T (log2 domain; Q pre-scaled)
        float sacc[8][4];
#pragma unroll
        for (int ni = 0; ni < 8; ni++)
#pragma unroll
            for (int e = 0; e < 4; e++) sacc[ni][e] = 0.f;

#pragma unroll
        for (int kk = 0; kk < 8; kk++) {
#pragma unroll
            for (int ni = 0; ni < 8; ni++) {
                const unsigned* b = Kb + (ni * 8 + fr) * ASTRIDE + kk * 8 + fc;
                unsigned bf[2] = {b[0], b[4]};
                MMA_TF32(sacc[ni], aq[kk], bf);
            }
        }

        // Warp-local softmax
        const bool need_mask = (k0 + 63 > q0);
#pragma unroll
        for (int h = 0; h < 2; h++) {
            const int rg = q0 + rbase + h * 8;
            float rm = -1e30f;
#pragma unroll
            for (int ni = 0; ni < 8; ni++)
#pragma unroll
            for (int e = 0; e < 2; e++) {
                float s = sacc[ni][h * 2 + e];
                if (need_mask && (k0 + ni * 8 + fc * 2 + e > rg)) s = -1e30f;
                sacc[ni][h * 2 + e] = s;
                rm = fmaxf(rm, s);
            }
            rm = fmaxf(rm, __shfl_xor_sync(0xffffffffu, rm, 1));
            rm = fmaxf(rm, __shfl_xor_sync(0xffffffffu, rm, 2));
            float mnew = fmaxf(m_i[h], rm);
            float al = exp2_fast(m_i[h] - mnew);
            m_i[h] = mnew;
            float rs = 0.f;
#pragma unroll
            for (int ni = 0; ni < 8; ni++) {
                float p0 = exp2_fast(sacc[ni][h * 2 + 0] - mnew);
                float p1 = exp2_fast(sacc[ni][h * 2 + 1] - mnew);
                rs += p0 + p1;
                *(uint2*)&Ps[(rbase + h * 8) * ASTRIDE + ni * 8 + fc * 2] =
                    make_uint2(f2tf32(p0), f2tf32(p1));
            }
            rs += __shfl_xor_sync(0xffffffffu, rs, 1);
            rs += __shfl_xor_sync(0xffffffffu, rs, 2);
            l_i[h] = l_i[h] * al + rs;
#pragma unroll
            for (int ni = 0; ni < 8; ni++) {
                O[ni][h * 2 + 0] *= al;
                O[ni][h * 2 + 1] *= al;
            }
        }
        __syncwarp();

        // O += P @ V
#pragma unroll
        for (int kk = 0; kk < 8; kk++) {
            unsigned af[4];
            {
                const unsigned* b = &Ps[rbase * ASTRIDE + kk * 8 + fc];
                af[0] = b[0];
                af[1] = b[8 * ASTRIDE];
                af[2] = b[4];
                af[3] = b[8 * ASTRIDE + 4];
            }
#pragma unroll
            for (int ni = 0; ni < 8; ni++) {
                const unsigned* b = Vb + (ni * 8 + fr) * ASTRIDE + kk * 8 + fc;
                unsigned bf[2] = {b[0], b[4]};
                MMA_TF32(O[ni], af, bf);
            }
        }
    }

    // Epilogue: normalize, store tf32 bits to [B*T, C]
    const int b = bh >> 4;
    const int h = bh & 15;
#pragma unroll
    for (int hh = 0; hh < 2; hh++) {
        float linv = 1.0f / l_i[hh];
        int row = q0 + rbase + hh * 8;
        unsigned* op = (unsigned*)g_att + ((size_t)(b * TT) + row) * DIMC + h * HDIM;
#pragma unroll
        for (int ni = 0; ni < 8; ni++) {
            *(uint2*)(op + ni * 8 + fc * 2) =
                make_uint2(f2tf32(O[ni][hh * 2 + 0] * linv),
                           f2tf32(O[ni][hh * 2 + 1] * linv));
        }
    }
}

// ---------------------------------------------------------------------------
extern "C" void kernel_launch(void* const* d_in, const int* in_sizes, int n_in,
                              void* d_out, int out_size)
{
    const float* x  = (const float*)d_in[0];
    // d_in[1] = mask (unused; causal applied analytically)
    const float* wq = (const float*)d_in[2];
    const float* wk = (const float*)d_in[3];
    const float* wv = (const float*)d_in[4];
    const float* wo = (const float*)d_in[5];
    float* out = (float*)d_out;

    float *dq, *dk, *dvt, *datt;
    unsigned *dxc, *dwc;
    cudaGetSymbolAddress((void**)&dq,   g_q);
    cudaGetSymbolAddress((void**)&dk,   g_k);
    cudaGetSymbolAddress((void**)&dvt,  g_vt);
    cudaGetSymbolAddress((void**)&datt, g_att);
    cudaGetSymbolAddress((void**)&dxc,  g_xc);
    cudaGetSymbolAddress((void**)&dwc,  g_wc);

    cudaFuncSetAttribute(attn_kernel,
                         cudaFuncAttributeMaxDynamicSharedMemorySize,
                         ATTN_SMEM_BYTES);
    cudaFuncSetAttribute(attn_kernel,
                         cudaFuncAttributePreferredSharedMemoryCarveout, 100);
    cudaFuncSetAttribute(gemm_kernel,
                         cudaFuncAttributeMaxDynamicSharedMemorySize,
                         GSM_BYTES);
    cudaFuncSetAttribute(gemm_kernel,
                         cudaFuncAttributePreferredSharedMemoryCarveout, 100);

    // Prepass: round x + weights to tf32 (wq pre-scaled by 0.125*log2e)
    conv_in_kernel<<<(XF4 + 4 * WF4) / 256, 256>>>(x, wq, wk, wv, wo);

    // QKV projections (tf32-bit outputs; V transposed)
    gemm_kernel<<<dim3(8, 64, 3), 256, GSM_BYTES>>>(
        dxc, dwc, dwc + DIMC * DIMC, dwc + 2 * DIMC * DIMC,
        dq, dk, dvt, 1);

    // Flash attention: grid (16 q-tiles of 128, 64 b*h)
    attn_kernel<<<dim3(16, 64), 256, ATTN_SMEM_BYTES>>>();

    // Output projection (g_att holds tf32 bits)
    gemm_kernel<<<dim3(8, 64, 1), 256, GSM_BYTES>>>(
        (unsigned*)datt, dwc + 3 * DIMC * DIMC, nullptr, nullptr,
        out, nullptr, nullptr, 0);
}

// round 15
// speedup vs baseline: 1.4576x; 1.0725x over previous
#include <cuda_runtime.h>
#include <cuda_bf16.h>
#include <cstdint>

#define DIMC 1024
#define NHEAD 16
#define HDIM 64
#define BB 4
#define TT 2048
#define MROWS (BB * TT)   // 8192

// Scratch (device globals — allocation-free contract)
__device__ float g_q[BB * NHEAD * TT * HDIM];   // [B,H,T,D]  tf32 bits (pre-scaled)
__device__ float g_k[BB * NHEAD * TT * HDIM];   // [B,H,T,D]  tf32 bits
__device__ float g_vt[BB * NHEAD * HDIM * TT];  // [B,H,D,T]  tf32 bits (transposed)
__device__ float g_att[MROWS * DIMC];           // [B*T, C]   tf32 bits
__device__ unsigned g_xc[MROWS * DIMC];         // tf32-rounded x
__device__ unsigned g_wc[4 * DIMC * DIMC];      // tf32-rounded wq*qsc|wk|wv|wo

__device__ __forceinline__ unsigned f2tf32(float x) {
    unsigned u;
    asm("cvt.rna.tf32.f32 %0, %1;" : "=r"(u) : "f"(x));
    return u;
}

// 2^x on the FMA/ALU pipes (no MUFU). x <= 0 expected; clamped at -120.
__device__ __forceinline__ float exp2_fast(float x) {
    x = fmaxf(x, -120.f);
    float n = floorf(x);
    float f = x - n;
    float p = 1.78656e-4f;
    p = fmaf(p, f, 1.33336e-3f);
    p = fmaf(p, f, 9.61813e-3f);
    p = fmaf(p, f, 5.55041e-2f);
    p = fmaf(p, f, 2.40226507e-1f);
    p = fmaf(p, f, 6.93147181e-1f);
    p = fmaf(p, f, 1.0f);
    return __uint_as_float(__float_as_uint(p) + (((int)n) << 23));
}

#define MMA_TF32(d, a, b)                                                    \
    asm volatile("mma.sync.aligned.m16n8k8.row.col.f32.tf32.tf32.f32 "        \
                 "{%0,%1,%2,%3}, {%4,%5,%6,%7}, {%8,%9}, {%0,%1,%2,%3};"      \
                 : "+f"(d[0]), "+f"(d[1]), "+f"(d[2]), "+f"(d[3])             \
                 : "r"(a[0]), "r"(a[1]), "r"(a[2]), "r"(a[3]),                \
                   "r"(b[0]), "r"(b[1]))

// tf32 fragment loaders (CUTLASS-style: b16 ldmatrix on 32-bit data).
#define LDSM_X4(R, a)                                                         \
    asm volatile("ldmatrix.sync.aligned.m8n8.x4.shared.b16 {%0,%1,%2,%3}, [%4];" \
                 : "=r"((R)[0]), "=r"((R)[1]), "=r"((R)[2]), "=r"((R)[3])     \
                 : "r"(a))
#define LDSM_X2(R, a)                                                         \
    asm volatile("ldmatrix.sync.aligned.m8n8.x2.shared.b16 {%0,%1}, [%2];"    \
                 : "=r"((R)[0]), "=r"((R)[1]) : "r"(a))

__device__ __forceinline__ uint32_t smem_u32(const void* p) {
    uint32_t a;
    asm("{ .reg .u64 t; cvta.to.shared.u64 t, %1; cvt.u32.u64 %0, t; }"
        : "=r"(a) : "l"(p));
    return a;
}

// ---------------------------------------------------------------------------
// Prepass: tf32-round x and weights; wq is pre-scaled by 0.125*log2(e).
// ---------------------------------------------------------------------------
#define XF4  (MROWS * DIMC / 4)
#define WF4  (DIMC * DIMC / 4)

__global__ __launch_bounds__(256) void conv_in_kernel(
    const float* __restrict__ x,
    const float* __restrict__ wq, const float* __restrict__ wk,
    const float* __restrict__ wv, const float* __restrict__ wo)
{
    int i = blockIdx.x * 256 + threadIdx.x;
    const float* src;
    unsigned* dst;
    int off;
    float sc = 1.0f;
    if (i < XF4) { src = x; dst = g_xc; off = i; }
    else {
        int j = i - XF4;
        int seg = j >> 18;
        off = j & (WF4 - 1);
        src = seg == 0 ? wq : seg == 1 ? wk : seg == 2 ? wv : wo;
        dst = g_wc + seg * (DIMC * DIMC);
        if (seg == 0) sc = 0.125f * 1.4426950408889634f;
    }
    float4 v = *(const float4*)(src + (size_t)off * 4);
    *(uint4*)(dst + (size_t)off * 4) =
        make_uint4(f2tf32(v.x * sc), f2tf32(v.y * sc),
                   f2tf32(v.z * sc), f2tf32(v.w * sc));
}

// ---------------------------------------------------------------------------
// TF32 mma.sync GEMM, cp.async 4-stage pipeline + ldmatrix fragment loads.
// ---------------------------------------------------------------------------
#define ROWW 20
#define STG_WORDS (128 * ROWW * 2)
#define NSTAGE_TOTAL (DIMC / 16)
#define GSM_BYTES (4 * STG_WORDS * 4)

__device__ __forceinline__ void stage_copy(
    const unsigned* __restrict__ A, const unsigned* __restrict__ W,
    int r0, int c0, uint32_t sb, int tid, int c)
{
    uint32_t base = sb + (uint32_t)(c & 3) * (STG_WORDS * 4);
#pragma unroll
    for (int j = 0; j < 2; j++) {
        int q = tid + j * 256;
        int row = q >> 2, kc = q & 3;
        const unsigned* srca = A + (size_t)(r0 + row) * DIMC + c * 16 + kc * 4;
        uint32_t dst = base + row * (ROWW * 4) + kc * 16;
        asm volatile("cp.async.cg.shared.global [%0], [%1], 16;"
                     :: "r"(dst), "l"(srca) : "memory");
        const unsigned* srcb = W + (size_t)(c0 + row) * DIMC + c * 16 + kc * 4;
        asm volatile("cp.async.cg.shared.global [%0], [%1], 16;"
                     :: "r"(dst + 128 * ROWW * 4), "l"(srcb) : "memory");
    }
}

__global__ __launch_bounds__(256, 2) void gemm_kernel(
    const unsigned* __restrict__ A,
    const unsigned* __restrict__ W0, const unsigned* __restrict__ W1,
    const unsigned* __restrict__ W2,
    float* __restrict__ D0, float* __restrict__ D1, float* __restrict__ D2,
    int qkv_mode)
{
    extern __shared__ unsigned smg[];
    const uint32_t sb = smem_u32(smg);

    const unsigned* W = W0;
    float* D = D0;
    if (blockIdx.z == 1) { W = W1; D = D1; }
    else if (blockIdx.z == 2) { W = W2; D = D2; }

    const int tid  = threadIdx.x;
    const int lane = tid & 31;
    const int w    = tid >> 5;
    const int wm   = w >> 2;
    const int wn   = w & 3;
    const int r0 = blockIdx.y * 128;
    const int c0 = blockIdx.x * 128;

    const int fr = lane >> 2;
    const int fc = lane & 3;
    const int lrow = lane & 7;
    const int lsel = lane >> 3;          // 0..3

    // per-lane ldmatrix base byte offsets
    const uint32_t aoff = ((wm * 64 + lrow + (lsel & 1) * 8) * ROWW
                           + (lsel >> 1) * 4) * 4;
    const uint32_t boff = ((wn * 32 + lrow) * ROWW + (lsel & 1) * 4) * 4;

    float acc[4][4][4];
#pragma unroll
    for (int mi = 0; mi < 4; mi++)
#pragma unroll
        for (int ni = 0; ni < 4; ni++)
#pragma unroll
            for (int e = 0; e < 4; e++) acc[mi][ni][e] = 0.f;

    stage_copy(A, W, r0, c0, sb, tid, 0);
    asm volatile("cp.async.commit_group;" ::: "memory");
    stage_copy(A, W, r0, c0, sb, tid, 1);
    asm volatile("cp.async.commit_group;" ::: "memory");
    stage_copy(A, W, r0, c0, sb, tid, 2);
    asm volatile("cp.async.commit_group;" ::: "memory");

    for (int c = 0; c < NSTAGE_TOTAL; c++) {
        asm volatile("cp.async.wait_group 2;" ::: "memory");
        __syncthreads();

        const uint32_t Abase = sb + (uint32_t)(c & 3) * (STG_WORDS * 4);
        const uint32_t Bbase = Abase + 128 * ROWW * 4;

#pragma unroll
        for (int kk = 0; kk < 2; kk++) {
            unsigned af[4][4], bfr[4][2];
#pragma unroll
            for (int mi = 0; mi < 4; mi++)
                LDSM_X4(af[mi], Abase + aoff + (mi * 16 * ROWW + kk * 8) * 4);
#pragma unroll
            for (int ni = 0; ni < 4; ni++)
                LDSM_X2(bfr[ni], Bbase + boff + (ni * 8 * ROWW + kk * 8) * 4);
#pragma unroll
            for (int mi = 0; mi < 4; mi++)
#pragma unroll
                for (int ni = 0; ni < 4; ni++)
                    MMA_TF32(acc[mi][ni], af[mi], bfr[ni]);
        }

        if (c + 3 < NSTAGE_TOTAL)
            stage_copy(A, W, r0, c0, sb, tid, c + 3);
        asm volatile("cp.async.commit_group;" ::: "memory");
    }

    if (!qkv_mode) {
#pragma unroll
        for (int mi = 0; mi < 4; mi++) {
            int r = r0 + wm * 64 + mi * 16 + fr;
#pragma unroll
            for (int ni = 0; ni < 4; ni++) {
                int c = c0 + wn * 32 + ni * 8 + fc * 2;
                *(float2*)(D + (size_t)r * DIMC + c) =
                    make_float2(acc[mi][ni][0], acc[mi][ni][1]);
                *(float2*)(D + (size_t)(r + 8) * DIMC + c) =
                    make_float2(acc[mi][ni][2], acc[mi][ni][3]);
            }
        }
    } else if (blockIdx.z != 2) {
#pragma unroll
        for (int mi = 0; mi < 4; mi++) {
            int row = r0 + wm * 64 + mi * 16 + fr;
#pragma unroll
            for (int half = 0; half < 2; half++) {
                int rr = row + half * 8;
                int b = rr >> 11;
                int t = rr & 2047;
#pragma unroll
                for (int ni = 0; ni < 4; ni++) {
                    int cc = wn * 32 + ni * 8 + fc * 2;
                    int h = blockIdx.x * 2 + (cc >> 6);
                    int d = cc & 63;
                    size_t idx = (((size_t)(b * NHEAD + h) * TT + t) * HDIM) + d;
                    unsigned u0 = f2tf32(acc[mi][ni][half * 2 + 0]);
                    unsigned u1 = f2tf32(acc[mi][ni][half * 2 + 1]);
                    *(uint2*)((unsigned*)D + idx) = make_uint2(u0, u1);
                }
            }
        }
    } else {
#pragma unroll
        for (int mi = 0; mi < 4; mi++) {
            int row = r0 + wm * 64 + mi * 16 + fr;
#pragma unroll
            for (int half = 0; half < 2; half++) {
                int rr = row + half * 8;
                int b = rr >> 11;
                int t = rr & 2047;
#pragma unroll
                for (int ni = 0; ni < 4; ni++) {
                    int cc = wn * 32 + ni * 8 + fc * 2;
                    int h = blockIdx.x * 2 + (cc >> 6);
                    int d = cc & 63;
                    size_t base = ((size_t)(b * NHEAD + h) * HDIM + d) * TT + t;
                    ((unsigned*)D)[base]      = f2tf32(acc[mi][ni][half * 2 + 0]);
                    ((unsigned*)D)[base + TT] = f2tf32(acc[mi][ni][half * 2 + 1]);
                }
            }
        }
    }
}

// ---------------------------------------------------------------------------
// Flash attention: Q frags in registers; K/V double-buffered via cp.async;
// ldmatrix fragment loads. BQ=128, 2 CTAs/SM.
// ---------------------------------------------------------------------------
#define ASTRIDE 68
#define KVW (64 * ASTRIDE)
#define KVBUF (2 * KVW)
#define ATTN_SMEM_BYTES ((2 * KVBUF + 128 * ASTRIDE) * 4)

__device__ __forceinline__ void stage_kv(
    const unsigned* __restrict__ Kg, const unsigned* __restrict__ Vg,
    uint32_t sb, int tid, int k0, int buf)
{
    uint32_t base = sb + (uint32_t)buf * (KVBUF * 4);
#pragma unroll
    for (int j = 0; j < 4; j++) {
        int u = tid + j * 256;
        int row = u >> 4;
        int ch  = u & 15;
        const unsigned* sk = Kg + (size_t)(k0 + row) * HDIM + ch * 4;
        uint32_t dst = base + row * (ASTRIDE * 4) + ch * 16;
        asm volatile("cp.async.cg.shared.global [%0], [%1], 16;"
                     :: "r"(dst), "l"(sk) : "memory");
        const unsigned* sv = Vg + (size_t)row * TT + k0 + ch * 4;
        asm volatile("cp.async.cg.shared.global [%0], [%1], 16;"
                     :: "r"(dst + KVW * 4), "l"(sv) : "memory");
    }
}

__global__ __launch_bounds__(256, 2) void attn_kernel()
{
    extern __shared__ unsigned smu[];
    const uint32_t sb = smem_u32(smu);
    unsigned* Ps = smu + 2 * KVBUF;
    const uint32_t psb = sb + 2 * KVBUF * 4;

    const int tid  = threadIdx.x;
    const int lane = tid & 31;
    const int w    = tid >> 5;
    const int fr   = lane >> 2;
    const int fc   = lane & 3;
    const int lrow = lane & 7;
    const int lsel = lane >> 3;

    const int bh = blockIdx.y;
    const int q0 = (gridDim.x - 1 - blockIdx.x) * 128;

    const unsigned* Qg = (const unsigned*)g_q + (size_t)bh * TT * HDIM;
    const unsigned* Kg = (const unsigned*)g_k + (size_t)bh * TT * HDIM;
    const unsigned* Vg = (const unsigned*)g_vt + (size_t)bh * HDIM * TT;

    const int rbase = w * 16 + fr;

    // ldmatrix per-lane base byte offsets
    const uint32_t kvoff = (lrow * ASTRIDE + (lsel & 1) * 4) * 4;   // B-side x2
    const uint32_t poff  = ((w * 16 + lrow + (lsel & 1) * 8) * ASTRIDE
                            + (lsel >> 1) * 4) * 4;                  // P x4

    // Q fragments -> registers (one-time)
    unsigned aq[8][4];
    {
        const unsigned* q0p = Qg + (size_t)(q0 + rbase) * HDIM;
        const unsigned* q1p = q0p + 8 * HDIM;
#pragma unroll
        for (int kk = 0; kk < 8; kk++) {
            aq[kk][0] = q0p[kk * 8 + fc];
            aq[kk][1] = q1p[kk * 8 + fc];
            aq[kk][2] = q0p[kk * 8 + fc + 4];
            aq[kk][3] = q1p[kk * 8 + fc + 4];
        }
    }

    float O[8][4];
#pragma unroll
    for (int ni = 0; ni < 8; ni++)
#pragma unroll
        for (int e = 0; e < 4; e++) O[ni][e] = 0.f;
    float m_i[2] = {-1e30f, -1e30f};
    float l_i[2] = {0.f, 0.f};

    const int ntiles = (q0 >> 6) + 2;

    stage_kv(Kg, Vg, sb, tid, 0, 0);
    asm volatile("cp.async.commit_group;" ::: "memory");

    for (int kt = 0; kt < ntiles; kt++) {
        const int k0 = kt * 64;
        asm volatile("cp.async.wait_group 0;" ::: "memory");
        __syncthreads();

        if (kt + 1 < ntiles) {
            stage_kv(Kg, Vg, sb, tid, k0 + 64, (kt + 1) & 1);
            asm volatile("cp.async.commit_group;" ::: "memory");
        }

        const uint32_t Kbase = sb + (uint32_t)(kt & 1) * (KVBUF * 4);
        const uint32_t Vbase = Kbase + KVW * 4;

        // S = Q @ K^T
        float sacc[8][4];
#pragma unroll
        for (int ni = 0; ni < 8; ni++)
#pragma unroll
            for (int e = 0; e < 4; e++) sacc[ni][e] = 0.f;

#pragma unroll
        for (int kk = 0; kk < 8; kk++) {
#pragma unroll
            for (int ni = 0; ni < 8; ni++) {
                unsigned bf[2];
                LDSM_X2(bf, Kbase + kvoff + (ni * 8 * ASTRIDE + kk * 8) * 4);
                MMA_TF32(sacc[ni], aq[kk], bf);
            }
        }

        // Warp-local softmax
        const bool need_mask = (k0 + 63 > q0);
#pragma unroll
        for (int h = 0; h < 2; h++) {
            const int rg = q0 + rbase + h * 8;
            float rm = -1e30f;
#pragma unroll
            for (int ni = 0; ni < 8; ni++)
#pragma unroll
            for (int e = 0; e < 2; e++) {
                float s = sacc[ni][h * 2 + e];
                if (need_mask && (k0 + ni * 8 + fc * 2 + e > rg)) s = -1e30f;
                sacc[ni][h * 2 + e] = s;
                rm = fmaxf(rm, s);
            }
            rm = fmaxf(rm, __shfl_xor_sync(0xffffffffu, rm, 1));
            rm = fmaxf(rm, __shfl_xor_sync(0xffffffffu, rm, 2));
            float mnew = fmaxf(m_i[h], rm);
            float al = exp2_fast(m_i[h] - mnew);
            m_i[h] = mnew;
            float rs = 0.f;
#pragma unroll
            for (int ni = 0; ni < 8; ni++) {
                float p0 = exp2_fast(sacc[ni][h * 2 + 0] - mnew);
                float p1 = exp2_fast(sacc[ni][h * 2 + 1] - mnew);
                rs += p0 + p1;
                *(uint2*)&Ps[(rbase + h * 8) * ASTRIDE + ni * 8 + fc * 2] =
                    make_uint2(f2tf32(p0), f2tf32(p1));
            }
            rs += __shfl_xor_sync(0xffffffffu, rs, 1);
            rs += __shfl_xor_sync(0xffffffffu, rs, 2);
            l_i[h] = l_i[h] * al + rs;
#pragma unroll
            for (int ni = 0; ni < 8; ni++) {
                O[ni][h * 2 + 0] *= al;
                O[ni][h * 2 + 1] *= al;
            }
        }
        __syncwarp();

        // O += P @ V
#pragma unroll
        for (int kk = 0; kk < 8; kk++) {
            unsigned af[4];
            LDSM_X4(af, psb + poff + kk * 8 * 4);
#pragma unroll
            for (int ni = 0; ni < 8; ni++) {
                unsigned bf[2];
                LDSM_X2(bf, Vbase + kvoff + (ni * 8 * ASTRIDE + kk * 8) * 4);
                MMA_TF32(O[ni], af, bf);
            }
        }
    }

    // Epilogue: normalize, store tf32 bits to [B*T, C]
    const int b = bh >> 4;
    const int h = bh & 15;
#pragma unroll
    for (int hh = 0; hh < 2; hh++) {
        float linv = 1.0f / l_i[hh];
        int row = q0 + rbase + hh * 8;
        unsigned* op = (unsigned*)g_att + ((size_t)(b * TT) + row) * DIMC + h * HDIM;
#pragma unroll
        for (int ni = 0; ni < 8; ni++) {
            *(uint2*)(op + ni * 8 + fc * 2) =
                make_uint2(f2tf32(O[ni][hh * 2 + 0] * linv),
                           f2tf32(O[ni][hh * 2 + 1] * linv));
        }
    }
}

// ---------------------------------------------------------------------------
extern "C" void kernel_launch(void* const* d_in, const int* in_sizes, int n_in,
                              void* d_out, int out_size)
{
    const float* x  = (const float*)d_in[0];
    // d_in[1] = mask (unused; causal applied analytically)
    const float* wq = (const float*)d_in[2];
    const float* wk = (const float*)d_in[3];
    const float* wv = (const float*)d_in[4];
    const float* wo = (const float*)d_in[5];
    float* out = (float*)d_out;

    float *dq, *dk, *dvt, *datt;
    unsigned *dxc, *dwc;
    cudaGetSymbolAddress((void**)&dq,   g_q);
    cudaGetSymbolAddress((void**)&dk,   g_k);
    cudaGetSymbolAddress((void**)&dvt,  g_vt);
    cudaGetSymbolAddress((void**)&datt, g_att);
    cudaGetSymbolAddress((void**)&dxc,  g_xc);
    cudaGetSymbolAddress((void**)&dwc,  g_wc);

    cudaFuncSetAttribute(attn_kernel,
                         cudaFuncAttributeMaxDynamicSharedMemorySize,
                         ATTN_SMEM_BYTES);
    cudaFuncSetAttribute(attn_kernel,
                         cudaFuncAttributePreferredSharedMemoryCarveout, 100);
    cudaFuncSetAttribute(gemm_kernel,
                         cudaFuncAttributeMaxDynamicSharedMemorySize,
                         GSM_BYTES);
    cudaFuncSetAttribute(gemm_kernel,
                         cudaFuncAttributePreferredSharedMemoryCarveout, 100);

    // Prepass: round x + weights to tf32 (wq pre-scaled by 0.125*log2e)
    conv_in_kernel<<<(XF4 + 4 * WF4) / 256, 256>>>(x, wq, wk, wv, wo);

    // QKV projections (tf32-bit outputs; V transposed)
    gemm_kernel<<<dim3(8, 64, 3), 256, GSM_BYTES>>>(
        dxc, dwc, dwc + DIMC * DIMC, dwc + 2 * DIMC * DIMC,
        dq, dk, dvt, 1);

    // Flash attention: grid (16 q-tiles of 128, 64 b*h)
    attn_kernel<<<dim3(16, 64), 256, ATTN_SMEM_BYTES>>>();

    // Output projection (g_att holds tf32 bits)
    gemm_kernel<<<dim3(8, 64, 1), 256, GSM_BYTES>>>(
        (unsigned*)datt, dwc + 3 * DIMC * DIMC, nullptr, nullptr,
        out, nullptr, nullptr, 0);
}

// round 16
// speedup vs baseline: 1.4582x; 1.0004x over previous
#include <cuda_runtime.h>
#include <cuda_bf16.h>
#include <cstdint>

#define DIMC 1024
#define NHEAD 16
#define HDIM 64
#define BB 4
#define TT 2048
#define MROWS (BB * TT)   // 8192

// Scratch (device globals — allocation-free contract)
__device__ float g_q[BB * NHEAD * TT * HDIM];   // [B,H,T,D]  tf32 bits (pre-scaled)
__device__ float g_k[BB * NHEAD * TT * HDIM];   // [B,H,T,D]  tf32 bits
__device__ float g_vt[BB * NHEAD * HDIM * TT];  // [B,H,D,T]  tf32 bits (transposed)
__device__ float g_att[MROWS * DIMC];           // [B*T, C]   tf32 bits
__device__ unsigned g_xc[MROWS * DIMC];         // tf32-rounded x
__device__ unsigned g_wc[4 * DIMC * DIMC];      // tf32-rounded wq*qsc|wk|wv|wo

__device__ __forceinline__ unsigned f2tf32(float x) {
    unsigned u;
    asm("cvt.rna.tf32.f32 %0, %1;" : "=r"(u) : "f"(x));
    return u;
}

// 2^x on the FMA/ALU pipes (no MUFU). x <= 0 expected; clamped at -120.
__device__ __forceinline__ float exp2_fast(float x) {
    x = fmaxf(x, -120.f);
    float n = floorf(x);
    float f = x - n;
    float p = 1.78656e-4f;
    p = fmaf(p, f, 1.33336e-3f);
    p = fmaf(p, f, 9.61813e-3f);
    p = fmaf(p, f, 5.55041e-2f);
    p = fmaf(p, f, 2.40226507e-1f);
    p = fmaf(p, f, 6.93147181e-1f);
    p = fmaf(p, f, 1.0f);
    return __uint_as_float(__float_as_uint(p) + (((int)n) << 23));
}

#define MMA_TF32(d, a, b)                                                    \
    asm volatile("mma.sync.aligned.m16n8k8.row.col.f32.tf32.tf32.f32 "        \
                 "{%0,%1,%2,%3}, {%4,%5,%6,%7}, {%8,%9}, {%0,%1,%2,%3};"      \
                 : "+f"(d[0]), "+f"(d[1]), "+f"(d[2]), "+f"(d[3])             \
                 : "r"(a[0]), "r"(a[1]), "r"(a[2]), "r"(a[3]),                \
                   "r"(b[0]), "r"(b[1]))

// tf32 fragment loaders (CUTLASS-style: b16 ldmatrix on 32-bit data).
#define LDSM_X4(R, a)                                                         \
    asm volatile("ldmatrix.sync.aligned.m8n8.x4.shared.b16 {%0,%1,%2,%3}, [%4];" \
                 : "=r"((R)[0]), "=r"((R)[1]), "=r"((R)[2]), "=r"((R)[3])     \
                 : "r"(a))

__device__ __forceinline__ uint32_t smem_u32(const void* p) {
    uint32_t a;
    asm("{ .reg .u64 t; cvta.to.shared.u64 t, %1; cvt.u32.u64 %0, t; }"
        : "=r"(a) : "l"(p));
    return a;
}

// ---------------------------------------------------------------------------
// Prepass: tf32-round x and weights; wq is pre-scaled by 0.125*log2(e).
// ---------------------------------------------------------------------------
#define XF4  (MROWS * DIMC / 4)
#define WF4  (DIMC * DIMC / 4)

__global__ __launch_bounds__(256) void conv_in_kernel(
    const float* __restrict__ x,
    const float* __restrict__ wq, const float* __restrict__ wk,
    const float* __restrict__ wv, const float* __restrict__ wo)
{
    int i = blockIdx.x * 256 + threadIdx.x;
    const float* src;
    unsigned* dst;
    int off;
    float sc = 1.0f;
    if (i < XF4) { src = x; dst = g_xc; off = i; }
    else {
        int j = i - XF4;
        int seg = j >> 18;
        off = j & (WF4 - 1);
        src = seg == 0 ? wq : seg == 1 ? wk : seg == 2 ? wv : wo;
        dst = g_wc + seg * (DIMC * DIMC);
        if (seg == 0) sc = 0.125f * 1.4426950408889634f;
    }
    float4 v = *(const float4*)(src + (size_t)off * 4);
    *(uint4*)(dst + (size_t)off * 4) =
        make_uint4(f2tf32(v.x * sc), f2tf32(v.y * sc),
                   f2tf32(v.z * sc), f2tf32(v.w * sc));
}

// ---------------------------------------------------------------------------
// TF32 mma.sync GEMM, cp.async 4-stage pipeline + ldmatrix.x4 fragments.
// ---------------------------------------------------------------------------
#define ROWW 20
#define STG_WORDS (128 * ROWW * 2)
#define NSTAGE_TOTAL (DIMC / 16)
#define GSM_BYTES (4 * STG_WORDS * 4)

__device__ __forceinline__ void stage_copy(
    const unsigned* __restrict__ A, const unsigned* __restrict__ W,
    int r0, int c0, uint32_t sb, int tid, int c)
{
    uint32_t base = sb + (uint32_t)(c & 3) * (STG_WORDS * 4);
#pragma unroll
    for (int j = 0; j < 2; j++) {
        int q = tid + j * 256;
        int row = q >> 2, kc = q & 3;
        const unsigned* srca = A + (size_t)(r0 + row) * DIMC + c * 16 + kc * 4;
        uint32_t dst = base + row * (ROWW * 4) + kc * 16;
        asm volatile("cp.async.cg.shared.global [%0], [%1], 16;"
                     :: "r"(dst), "l"(srca) : "memory");
        const unsigned* srcb = W + (size_t)(c0 + row) * DIMC + c * 16 + kc * 4;
        asm volatile("cp.async.cg.shared.global [%0], [%1], 16;"
                     :: "r"(dst + 128 * ROWW * 4), "l"(srcb) : "memory");
    }
}

__global__ __launch_bounds__(256, 2) void gemm_kernel(
    const unsigned* __restrict__ A,
    const unsigned* __restrict__ W0, const unsigned* __restrict__ W1,
    const unsigned* __restrict__ W2,
    float* __restrict__ D0, float* __restrict__ D1, float* __restrict__ D2,
    int qkv_mode)
{
    extern __shared__ unsigned smg[];
    const uint32_t sb = smem_u32(smg);

    const unsigned* W = W0;
    float* D = D0;
    if (blockIdx.z == 1) { W = W1; D = D1; }
    else if (blockIdx.z == 2) { W = W2; D = D2; }

    const int tid  = threadIdx.x;
    const int lane = tid & 31;
    const int w    = tid >> 5;
    const int wm   = w >> 2;
    const int wn   = w & 3;
    const int r0 = blockIdx.y * 128;
    const int c0 = blockIdx.x * 128;

    const int fr = lane >> 2;
    const int fc = lane & 3;
    const int lrow = lane & 7;
    const int lsel = lane >> 3;          // 0..3

    // per-lane ldmatrix base byte offsets
    const uint32_t aoff = ((wm * 64 + lrow + (lsel & 1) * 8) * ROWW
                           + (lsel >> 1) * 4) * 4;
    // B x4: matrix m -> col-pair (m>>1), k-half (m&1)
    const uint32_t boff = ((wn * 32 + (lsel >> 1) * 8 + lrow) * ROWW
                           + (lsel & 1) * 4) * 4;

    float acc[4][4][4];
#pragma unroll
    for (int mi = 0; mi < 4; mi++)
#pragma unroll
        for (int ni = 0; ni < 4; ni++)
#pragma unroll
            for (int e = 0; e < 4; e++) acc[mi][ni][e] = 0.f;

    stage_copy(A, W, r0, c0, sb, tid, 0);
    asm volatile("cp.async.commit_group;" ::: "memory");
    stage_copy(A, W, r0, c0, sb, tid, 1);
    asm volatile("cp.async.commit_group;" ::: "memory");
    stage_copy(A, W, r0, c0, sb, tid, 2);
    asm volatile("cp.async.commit_group;" ::: "memory");

    for (int c = 0; c < NSTAGE_TOTAL; c++) {
        asm volatile("cp.async.wait_group 2;" ::: "memory");
        __syncthreads();

        // prefetch first: DMA overlaps the MMA work below
        if (c + 3 < NSTAGE_TOTAL)
            stage_copy(A, W, r0, c0, sb, tid, c + 3);
        asm volatile("cp.async.commit_group;" ::: "memory");

        const uint32_t Abase = sb + (uint32_t)(c & 3) * (STG_WORDS * 4);
        const uint32_t Bbase = Abase + 128 * ROWW * 4;

#pragma unroll
        for (int kk = 0; kk < 2; kk++) {
            unsigned af[4][4], bfr[4][2];
#pragma unroll
            for (int mi = 0; mi < 4; mi++)
                LDSM_X4(af[mi], Abase + aoff + (mi * 16 * ROWW + kk * 8) * 4);
#pragma unroll
            for (int np = 0; np < 2; np++) {
                unsigned t4[4];
                LDSM_X4(t4, Bbase + boff + (np * 16 * ROWW + kk * 8) * 4);
                bfr[2 * np][0] = t4[0]; bfr[2 * np][1] = t4[1];
                bfr[2 * np + 1][0] = t4[2]; bfr[2 * np + 1][1] = t4[3];
            }
#pragma unroll
            for (int mi = 0; mi < 4; mi++)
#pragma unroll
                for (int ni = 0; ni < 4; ni++)
                    MMA_TF32(acc[mi][ni], af[mi], bfr[ni]);
        }
    }

    if (!qkv_mode) {
#pragma unroll
        for (int mi = 0; mi < 4; mi++) {
            int r = r0 + wm * 64 + mi * 16 + fr;
#pragma unroll
            for (int ni = 0; ni < 4; ni++) {
                int c = c0 + wn * 32 + ni * 8 + fc * 2;
                *(float2*)(D + (size_t)r * DIMC + c) =
                    make_float2(acc[mi][ni][0], acc[mi][ni][1]);
                *(float2*)(D + (size_t)(r + 8) * DIMC + c) =
                    make_float2(acc[mi][ni][2], acc[mi][ni][3]);
            }
        }
    } else if (blockIdx.z != 2) {
#pragma unroll
        for (int mi = 0; mi < 4; mi++) {
            int row = r0 + wm * 64 + mi * 16 + fr;
#pragma unroll
            for (int half = 0; half < 2; half++) {
                int rr = row + half * 8;
                int b = rr >> 11;
                int t = rr & 2047;
#pragma unroll
                for (int ni = 0; ni < 4; ni++) {
                    int cc = wn * 32 + ni * 8 + fc * 2;
                    int h = blockIdx.x * 2 + (cc >> 6);
                    int d = cc & 63;
                    size_t idx = (((size_t)(b * NHEAD + h) * TT + t) * HDIM) + d;
                    unsigned u0 = f2tf32(acc[mi][ni][half * 2 + 0]);
                    unsigned u1 = f2tf32(acc[mi][ni][half * 2 + 1]);
                    *(uint2*)((unsigned*)D + idx) = make_uint2(u0, u1);
                }
            }
        }
    } else {
#pragma unroll
        for (int mi = 0; mi < 4; mi++) {
            int row = r0 + wm * 64 + mi * 16 + fr;
#pragma unroll
            for (int half = 0; half < 2; half++) {
                int rr = row + half * 8;
                int b = rr >> 11;
                int t = rr & 2047;
#pragma unroll
                for (int ni = 0; ni < 4; ni++) {
                    int cc = wn * 32 + ni * 8 + fc * 2;
                    int h = blockIdx.x * 2 + (cc >> 6);
                    int d = cc & 63;
                    size_t base = ((size_t)(b * NHEAD + h) * HDIM + d) * TT + t;
                    ((unsigned*)D)[base]      = f2tf32(acc[mi][ni][half * 2 + 0]);
                    ((unsigned*)D)[base + TT] = f2tf32(acc[mi][ni][half * 2 + 1]);
                }
            }
        }
    }
}

// ---------------------------------------------------------------------------
// Flash attention: Q frags in registers; K/V double-buffered via cp.async;
// ldmatrix.x4 fragment loads throughout. BQ=128, 2 CTAs/SM.
// ---------------------------------------------------------------------------
#define ASTRIDE 68
#define KVW (64 * ASTRIDE)
#define KVBUF (2 * KVW)
#define ATTN_SMEM_BYTES ((2 * KVBUF + 128 * ASTRIDE) * 4)

__device__ __forceinline__ void stage_kv(
    const unsigned* __restrict__ Kg, const unsigned* __restrict__ Vg,
    uint32_t sb, int tid, int k0, int buf)
{
    uint32_t base = sb + (uint32_t)buf * (KVBUF * 4);
#pragma unroll
    for (int j = 0; j < 4; j++) {
        int u = tid + j * 256;
        int row = u >> 4;
        int ch  = u & 15;
        const unsigned* sk = Kg + (size_t)(k0 + row) * HDIM + ch * 4;
        uint32_t dst = base + row * (ASTRIDE * 4) + ch * 16;
        asm volatile("cp.async.cg.shared.global [%0], [%1], 16;"
                     :: "r"(dst), "l"(sk) : "memory");
        const unsigned* sv = Vg + (size_t)row * TT + k0 + ch * 4;
        asm volatile("cp.async.cg.shared.global [%0], [%1], 16;"
                     :: "r"(dst + KVW * 4), "l"(sv) : "memory");
    }
}

__global__ __launch_bounds__(256, 2) void attn_kernel()
{
    extern __shared__ unsigned smu[];
    const uint32_t sb = smem_u32(smu);
    unsigned* Ps = smu + 2 * KVBUF;
    const uint32_t psb = sb + 2 * KVBUF * 4;

    const int tid  = threadIdx.x;
    const int lane = tid & 31;
    const int w    = tid >> 5;
    const int fr   = lane >> 2;
    const int fc   = lane & 3;
    const int lrow = lane & 7;
    const int lsel = lane >> 3;

    const int bh = blockIdx.y;
    const int q0 = (gridDim.x - 1 - blockIdx.x) * 128;

    const unsigned* Qg = (const unsigned*)g_q + (size_t)bh * TT * HDIM;
    const unsigned* Kg = (const unsigned*)g_k + (size_t)bh * TT * HDIM;
    const unsigned* Vg = (const unsigned*)g_vt + (size_t)bh * HDIM * TT;

    const int rbase = w * 16 + fr;

    // ldmatrix per-lane base byte offsets
    const uint32_t kvoff = (((lsel >> 1) * 8 + lrow) * ASTRIDE
                            + (lsel & 1) * 4) * 4;                   // K/V x4
    const uint32_t poff  = ((w * 16 + lrow + (lsel & 1) * 8) * ASTRIDE
                            + (lsel >> 1) * 4) * 4;                  // P x4

    // Q fragments -> registers (one-time)
    unsigned aq[8][4];
    {
        const unsigned* q0p = Qg + (size_t)(q0 + rbase) * HDIM;
        const unsigned* q1p = q0p + 8 * HDIM;
#pragma unroll
        for (int kk = 0; kk < 8; kk++) {
            aq[kk][0] = q0p[kk * 8 + fc];
            aq[kk][1] = q1p[kk * 8 + fc];
            aq[kk][2] = q0p[kk * 8 + fc + 4];
            aq[kk][3] = q1p[kk * 8 + fc + 4];
        }
    }

    float O[8][4];
#pragma unroll
    for (int ni = 0; ni < 8; ni++)
#pragma unroll
        for (int e = 0; e < 4; e++) O[ni][e] = 0.f;
    float m_i[2] = {-1e30f, -1e30f};
    float l_i[2] = {0.f, 0.f};

    const int ntiles = (q0 >> 6) + 2;

    stage_kv(Kg, Vg, sb, tid, 0, 0);
    asm volatile("cp.async.commit_group;" ::: "memory");

    for (int kt = 0; kt < ntiles; kt++) {
        const int k0 = kt * 64;
        asm volatile("cp.async.wait_group 0;" ::: "memory");
        __syncthreads();

        if (kt + 1 < ntiles) {
            stage_kv(Kg, Vg, sb, tid, k0 + 64, (kt + 1) & 1);
            asm volatile("cp.async.commit_group;" ::: "memory");
        }

        const uint32_t Kbase = sb + (uint32_t)(kt & 1) * (KVBUF * 4);
        const uint32_t Vbase = Kbase + KVW * 4;

        // S = Q @ K^T
        float sacc[8][4];
#pragma unroll
        for (int ni = 0; ni < 8; ni++)
#pragma unroll
            for (int e = 0; e < 4; e++) sacc[ni][e] = 0.f;

#pragma unroll
        for (int kk = 0; kk < 8; kk++) {
#pragma unroll
            for (int np = 0; np < 4; np++) {
                unsigned t4[4];
                LDSM_X4(t4, Kbase + kvoff + (np * 16 * ASTRIDE + kk * 8) * 4);
                unsigned b0[2] = {t4[0], t4[1]};
                unsigned b1[2] = {t4[2], t4[3]};
                MMA_TF32(sacc[2 * np], aq[kk], b0);
                MMA_TF32(sacc[2 * np + 1], aq[kk], b1);
            }
        }

        // Warp-local softmax
        const bool need_mask = (k0 + 63 > q0);
#pragma unroll
        for (int h = 0; h < 2; h++) {
            const int rg = q0 + rbase + h * 8;
            float rm = -1e30f;
#pragma unroll
            for (int ni = 0; ni < 8; ni++)
#pragma unroll
            for (int e = 0; e < 2; e++) {
                float s = sacc[ni][h * 2 + e];
                if (need_mask && (k0 + ni * 8 + fc * 2 + e > rg)) s = -1e30f;
                sacc[ni][h * 2 + e] = s;
                rm = fmaxf(rm, s);
            }
            rm = fmaxf(rm, __shfl_xor_sync(0xffffffffu, rm, 1));
            rm = fmaxf(rm, __shfl_xor_sync(0xffffffffu, rm, 2));
            float mnew = fmaxf(m_i[h], rm);
            float al = exp2_fast(m_i[h] - mnew);
            m_i[h] = mnew;
            float rs = 0.f;
#pragma unroll
            for (int ni = 0; ni < 8; ni++) {
                float p0 = exp2_fast(sacc[ni][h * 2 + 0] - mnew);
                float p1 = exp2_fast(sacc[ni][h * 2 + 1] - mnew);
                rs += p0 + p1;
                *(uint2*)&Ps[(rbase + h * 8) * ASTRIDE + ni * 8 + fc * 2] =
                    make_uint2(f2tf32(p0), f2tf32(p1));
            }
            rs += __shfl_xor_sync(0xffffffffu, rs, 1);
            rs += __shfl_xor_sync(0xffffffffu, rs, 2);
            l_i[h] = l_i[h] * al + rs;
#pragma unroll
            for (int ni = 0; ni < 8; ni++) {
                O[ni][h * 2 + 0] *= al;
                O[ni][h * 2 + 1] *= al;
            }
        }
        __syncwarp();

        // O += P @ V
#pragma unroll
        for (int kk = 0; kk < 8; kk++) {
            unsigned af[4];
            LDSM_X4(af, psb + poff + kk * 8 * 4);
#pragma unroll
            for (int np = 0; np < 4; np++) {
                unsigned t4[4];
                LDSM_X4(t4, Vbase + kvoff + (np * 16 * ASTRIDE + kk * 8) * 4);
                unsigned b0[2] = {t4[0], t4[1]};
                unsigned b1[2] = {t4[2], t4[3]};
                MMA_TF32(O[2 * np], af, b0);
                MMA_TF32(O[2 * np + 1], af, b1);
            }
        }
    }

    // Epilogue: normalize, store tf32 bits to [B*T, C]
    const int b = bh >> 4;
    const int h = bh & 15;
#pragma unroll
    for (int hh = 0; hh < 2; hh++) {
        float linv = 1.0f / l_i[hh];
        int row = q0 + rbase + hh * 8;
        unsigned* op = (unsigned*)g_att + ((size_t)(b * TT) + row) * DIMC + h * HDIM;
#pragma unroll
        for (int ni = 0; ni < 8; ni++) {
            *(uint2*)(op + ni * 8 + fc * 2) =
                make_uint2(f2tf32(O[ni][hh * 2 + 0] * linv),
                           f2tf32(O[ni][hh * 2 + 1] * linv));
        }
    }
}

// ---------------------------------------------------------------------------
extern "C" void kernel_launch(void* const* d_in, const int* in_sizes, int n_in,
                              void* d_out, int out_size)
{
    const float* x  = (const float*)d_in[0];
    // d_in[1] = mask (unused; causal applied analytically)
    const float* wq = (const float*)d_in[2];
    const float* wk = (const float*)d_in[3];
    const float* wv = (const float*)d_in[4];
    const float* wo = (const float*)d_in[5];
    float* out = (float*)d_out;

    float *dq, *dk, *dvt, *datt;
    unsigned *dxc, *dwc;
    cudaGetSymbolAddress((void**)&dq,   g_q);
    cudaGetSymbolAddress((void**)&dk,   g_k);
    cudaGetSymbolAddress((void**)&dvt,  g_vt);
    cudaGetSymbolAddress((void**)&datt, g_att);
    cudaGetSymbolAddress((void**)&dxc,  g_xc);
    cudaGetSymbolAddress((void**)&dwc,  g_wc);

    cudaFuncSetAttribute(attn_kernel,
                         cudaFuncAttributeMaxDynamicSharedMemorySize,
                         ATTN_SMEM_BYTES);
    cudaFuncSetAttribute(attn_kernel,
                         cudaFuncAttributePreferredSharedMemoryCarveout, 100);
    cudaFuncSetAttribute(gemm_kernel,
                         cudaFuncAttributeMaxDynamicSharedMemorySize,
                         GSM_BYTES);
    cudaFuncSetAttribute(gemm_kernel,
                         cudaFuncAttributePreferredSharedMemoryCarveout, 100);

    // Prepass: round x + weights to tf32 (wq pre-scaled by 0.125*log2e)
    conv_in_kernel<<<(XF4 + 4 * WF4) / 256, 256>>>(x, wq, wk, wv, wo);

    // QKV projections (tf32-bit outputs; V transposed)
    gemm_kernel<<<dim3(8, 64, 3), 256, GSM_BYTES>>>(
        dxc, dwc, dwc + DIMC * DIMC, dwc + 2 * DIMC * DIMC,
        dq, dk, dvt, 1);

    // Flash attention: grid (16 q-tiles of 128, 64 b*h)
    attn_kernel<<<dim3(16, 64), 256, ATTN_SMEM_BYTES>>>();

    // Output projection (g_att holds tf32 bits)
    gemm_kernel<<<dim3(8, 64, 1), 256, GSM_BYTES>>>(
        (unsigned*)datt, dwc + 3 * DIMC * DIMC, nullptr, nullptr,
        out, nullptr, nullptr, 0);
}

// round 17
// speedup vs baseline: 1.5132x; 1.0378x over previous
#include <cuda_runtime.h>
#include <cuda_bf16.h>
#include <cstdint>

#define DIMC 1024
#define NHEAD 16
#define HDIM 64
#define BB 4
#define TT 2048
#define MROWS (BB * TT)   // 8192

// Scratch (device globals — allocation-free contract)
__device__ float g_q[BB * NHEAD * TT * HDIM];   // [B,H,T,D]  tf32 bits (pre-scaled)
__device__ float g_k[BB * NHEAD * TT * HDIM];   // [B,H,T,D]  tf32 bits
__device__ float g_vt[BB * NHEAD * HDIM * TT];  // [B,H,D,T]  tf32 bits (transposed)
__device__ float g_att[MROWS * DIMC];           // [B*T, C]   tf32 bits
__device__ unsigned g_xc[MROWS * DIMC];         // tf32-rounded x
__device__ unsigned g_wc[4 * DIMC * DIMC];      // tf32-rounded wq*qsc|wk|wv|wo

__device__ __forceinline__ unsigned f2tf32(float x) {
    unsigned u;
    asm("cvt.rna.tf32.f32 %0, %1;" : "=r"(u) : "f"(x));
    return u;
}

// 2^x on the FMA/ALU pipes (no MUFU). x <= 0 expected; clamped at -120.
__device__ __forceinline__ float exp2_fast(float x) {
    x = fmaxf(x, -120.f);
    float n = floorf(x);
    float f = x - n;
    float p = 1.78656e-4f;
    p = fmaf(p, f, 1.33336e-3f);
    p = fmaf(p, f, 9.61813e-3f);
    p = fmaf(p, f, 5.55041e-2f);
    p = fmaf(p, f, 2.40226507e-1f);
    p = fmaf(p, f, 6.93147181e-1f);
    p = fmaf(p, f, 1.0f);
    return __uint_as_float(__float_as_uint(p) + (((int)n) << 23));
}

#define MMA_TF32(d, a, b)                                                    \
    asm volatile("mma.sync.aligned.m16n8k8.row.col.f32.tf32.tf32.f32 "        \
                 "{%0,%1,%2,%3}, {%4,%5,%6,%7}, {%8,%9}, {%0,%1,%2,%3};"      \
                 : "+f"(d[0]), "+f"(d[1]), "+f"(d[2]), "+f"(d[3])             \
                 : "r"(a[0]), "r"(a[1]), "r"(a[2]), "r"(a[3]),                \
                   "r"(b[0]), "r"(b[1]))

// tf32 fragment loader (CUTLASS-style: b16 ldmatrix on 32-bit data).
#define LDSM_X4(R, a)                                                         \
    asm volatile("ldmatrix.sync.aligned.m8n8.x4.shared.b16 {%0,%1,%2,%3}, [%4];" \
                 : "=r"((R)[0]), "=r"((R)[1]), "=r"((R)[2]), "=r"((R)[3])     \
                 : "r"(a))

__device__ __forceinline__ uint32_t smem_u32(const void* p) {
    uint32_t a;
    asm("{ .reg .u64 t; cvta.to.shared.u64 t, %1; cvt.u32.u64 %0, t; }"
        : "=r"(a) : "l"(p));
    return a;
}

// ---------------------------------------------------------------------------
// Prepass: tf32-round x and weights; wq is pre-scaled by 0.125*log2(e).
// ---------------------------------------------------------------------------
#define XF4  (MROWS * DIMC / 4)
#define WF4  (DIMC * DIMC / 4)

__global__ __launch_bounds__(256) void conv_in_kernel(
    const float* __restrict__ x,
    const float* __restrict__ wq, const float* __restrict__ wk,
    const float* __restrict__ wv, const float* __restrict__ wo)
{
    int i = blockIdx.x * 256 + threadIdx.x;
    const float* src;
    unsigned* dst;
    int off;
    float sc = 1.0f;
    if (i < XF4) { src = x; dst = g_xc; off = i; }
    else {
        int j = i - XF4;
        int seg = j >> 18;
        off = j & (WF4 - 1);
        src = seg == 0 ? wq : seg == 1 ? wk : seg == 2 ? wv : wo;
        dst = g_wc + seg * (DIMC * DIMC);
        if (seg == 0) sc = 0.125f * 1.4426950408889634f;
    }
    float4 v = *(const float4*)(src + (size_t)off * 4);
    *(uint4*)(dst + (size_t)off * 4) =
        make_uint4(f2tf32(v.x * sc), f2tf32(v.y * sc),
                   f2tf32(v.z * sc), f2tf32(v.w * sc));
}

// ---------------------------------------------------------------------------
// TF32 mma.sync GEMM: cp.async 3-stage ring, BK=32 per stage (64 MMAs/warp
// between barriers), ldmatrix.x4 fragments. 128x128 block, 256 threads.
// ---------------------------------------------------------------------------
#define ROWW 36                          // 32 data + 4 pad words per row
#define STG_WORDS (128 * ROWW * 2)       // 9216
#define NSTAGE_TOTAL (DIMC / 32)         // 32
#define GSM_BYTES (3 * STG_WORDS * 4)    // 110592

__device__ __forceinline__ void stage_copy(
    const unsigned* __restrict__ A, const unsigned* __restrict__ W,
    int r0, int c0, uint32_t sb, int tid, int c)
{
    uint32_t base = sb + (uint32_t)(c % 3) * (STG_WORDS * 4);
#pragma unroll
    for (int j = 0; j < 4; j++) {
        int u = tid + j * 256;           // 0..1023
        int row = u >> 3, ch = u & 7;    // 8 x 16B chunks per 32-float row
        const unsigned* srca = A + (size_t)(r0 + row) * DIMC + c * 32 + ch * 4;
        uint32_t dst = base + row * (ROWW * 4) + ch * 16;
        asm volatile("cp.async.cg.shared.global [%0], [%1], 16;"
                     :: "r"(dst), "l"(srca) : "memory");
        const unsigned* srcb = W + (size_t)(c0 + row) * DIMC + c * 32 + ch * 4;
        asm volatile("cp.async.cg.shared.global [%0], [%1], 16;"
                     :: "r"(dst + 128 * ROWW * 4), "l"(srcb) : "memory");
    }
}

__global__ __launch_bounds__(256, 2) void gemm_kernel(
    const unsigned* __restrict__ A,
    const unsigned* __restrict__ W0, const unsigned* __restrict__ W1,
    const unsigned* __restrict__ W2,
    float* __restrict__ D0, float* __restrict__ D1, float* __restrict__ D2,
    int qkv_mode)
{
    extern __shared__ unsigned smg[];
    const uint32_t sb = smem_u32(smg);

    const unsigned* W = W0;
    float* D = D0;
    if (blockIdx.z == 1) { W = W1; D = D1; }
    else if (blockIdx.z == 2) { W = W2; D = D2; }

    const int tid  = threadIdx.x;
    const int lane = tid & 31;
    const int w    = tid >> 5;
    const int wm   = w >> 2;
    const int wn   = w & 3;
    const int r0 = blockIdx.y * 128;
    const int c0 = blockIdx.x * 128;

    const int fr = lane >> 2;
    const int fc = lane & 3;
    const int lrow = lane & 7;
    const int lsel = lane >> 3;          // 0..3

    // per-lane ldmatrix base byte offsets
    const uint32_t aoff = ((wm * 64 + lrow + (lsel & 1) * 8) * ROWW
                           + (lsel >> 1) * 4) * 4;
    const uint32_t boff = ((wn * 32 + (lsel >> 1) * 8 + lrow) * ROWW
                           + (lsel & 1) * 4) * 4;

    float acc[4][4][4];
#pragma unroll
    for (int mi = 0; mi < 4; mi++)
#pragma unroll
        for (int ni = 0; ni < 4; ni++)
#pragma unroll
            for (int e = 0; e < 4; e++) acc[mi][ni][e] = 0.f;

    stage_copy(A, W, r0, c0, sb, tid, 0);
    asm volatile("cp.async.commit_group;" ::: "memory");
    stage_copy(A, W, r0, c0, sb, tid, 1);
    asm volatile("cp.async.commit_group;" ::: "memory");

    for (int c = 0; c < NSTAGE_TOTAL; c++) {
        asm volatile("cp.async.wait_group 1;" ::: "memory");
        __syncthreads();

        // prefetch next-next stage; DMA overlaps the 64 MMAs below
        if (c + 2 < NSTAGE_TOTAL)
            stage_copy(A, W, r0, c0, sb, tid, c + 2);
        asm volatile("cp.async.commit_group;" ::: "memory");

        const uint32_t Abase = sb + (uint32_t)(c % 3) * (STG_WORDS * 4);
        const uint32_t Bbase = Abase + 128 * ROWW * 4;

#pragma unroll
        for (int kk = 0; kk < 4; kk++) {
            unsigned af[4][4], bfr[4][2];
#pragma unroll
            for (int mi = 0; mi < 4; mi++)
                LDSM_X4(af[mi], Abase + aoff + (mi * 16 * ROWW + kk * 8) * 4);
#pragma unroll
            for (int np = 0; np < 2; np++) {
                unsigned t4[4];
                LDSM_X4(t4, Bbase + boff + (np * 16 * ROWW + kk * 8) * 4);
                bfr[2 * np][0] = t4[0]; bfr[2 * np][1] = t4[1];
                bfr[2 * np + 1][0] = t4[2]; bfr[2 * np + 1][1] = t4[3];
            }
#pragma unroll
            for (int mi = 0; mi < 4; mi++)
#pragma unroll
                for (int ni = 0; ni < 4; ni++)
                    MMA_TF32(acc[mi][ni], af[mi], bfr[ni]);
        }
    }

    if (!qkv_mode) {
#pragma unroll
        for (int mi = 0; mi < 4; mi++) {
            int r = r0 + wm * 64 + mi * 16 + fr;
#pragma unroll
            for (int ni = 0; ni < 4; ni++) {
                int c = c0 + wn * 32 + ni * 8 + fc * 2;
                *(float2*)(D + (size_t)r * DIMC + c) =
                    make_float2(acc[mi][ni][0], acc[mi][ni][1]);
                *(float2*)(D + (size_t)(r + 8) * DIMC + c) =
                    make_float2(acc[mi][ni][2], acc[mi][ni][3]);
            }
        }
    } else if (blockIdx.z != 2) {
#pragma unroll
        for (int mi = 0; mi < 4; mi++) {
            int row = r0 + wm * 64 + mi * 16 + fr;
#pragma unroll
            for (int half = 0; half < 2; half++) {
                int rr = row + half * 8;
                int b = rr >> 11;
                int t = rr & 2047;
#pragma unroll
                for (int ni = 0; ni < 4; ni++) {
                    int cc = wn * 32 + ni * 8 + fc * 2;
                    int h = blockIdx.x * 2 + (cc >> 6);
                    int d = cc & 63;
                    size_t idx = (((size_t)(b * NHEAD + h) * TT + t) * HDIM) + d;
                    unsigned u0 = f2tf32(acc[mi][ni][half * 2 + 0]);
                    unsigned u1 = f2tf32(acc[mi][ni][half * 2 + 1]);
                    *(uint2*)((unsigned*)D + idx) = make_uint2(u0, u1);
                }
            }
        }
    } else {
#pragma unroll
        for (int mi = 0; mi < 4; mi++) {
            int row = r0 + wm * 64 + mi * 16 + fr;
#pragma unroll
            for (int half = 0; half < 2; half++) {
                int rr = row + half * 8;
                int b = rr >> 11;
                int t = rr & 2047;
#pragma unroll
                for (int ni = 0; ni < 4; ni++) {
                    int cc = wn * 32 + ni * 8 + fc * 2;
                    int h = blockIdx.x * 2 + (cc >> 6);
                    int d = cc & 63;
                    size_t base = ((size_t)(b * NHEAD + h) * HDIM + d) * TT + t;
                    ((unsigned*)D)[base]      = f2tf32(acc[mi][ni][half * 2 + 0]);
                    ((unsigned*)D)[base + TT] = f2tf32(acc[mi][ni][half * 2 + 1]);
                }
            }
        }
    }
}

// ---------------------------------------------------------------------------
// Flash attention (unchanged from R16): Q frags in registers; K/V double-
// buffered via cp.async; ldmatrix.x4 fragments. BQ=128, 2 CTAs/SM.
// ---------------------------------------------------------------------------
#define ASTRIDE 68
#define KVW (64 * ASTRIDE)
#define KVBUF (2 * KVW)
#define ATTN_SMEM_BYTES ((2 * KVBUF + 128 * ASTRIDE) * 4)

__device__ __forceinline__ void stage_kv(
    const unsigned* __restrict__ Kg, const unsigned* __restrict__ Vg,
    uint32_t sb, int tid, int k0, int buf)
{
    uint32_t base = sb + (uint32_t)buf * (KVBUF * 4);
#pragma unroll
    for (int j = 0; j < 4; j++) {
        int u = tid + j * 256;
        int row = u >> 4;
        int ch  = u & 15;
        const unsigned* sk = Kg + (size_t)(k0 + row) * HDIM + ch * 4;
        uint32_t dst = base + row * (ASTRIDE * 4) + ch * 16;
        asm volatile("cp.async.cg.shared.global [%0], [%1], 16;"
                     :: "r"(dst), "l"(sk) : "memory");
        const unsigned* sv = Vg + (size_t)row * TT + k0 + ch * 4;
        asm volatile("cp.async.cg.shared.global [%0], [%1], 16;"
                     :: "r"(dst + KVW * 4), "l"(sv) : "memory");
    }
}

__global__ __launch_bounds__(256, 2) void attn_kernel()
{
    extern __shared__ unsigned smu[];
    const uint32_t sb = smem_u32(smu);
    unsigned* Ps = smu + 2 * KVBUF;
    const uint32_t psb = sb + 2 * KVBUF * 4;

    const int tid  = threadIdx.x;
    const int lane = tid & 31;
    const int w    = tid >> 5;
    const int fr   = lane >> 2;
    const int fc   = lane & 3;
    const int lrow = lane & 7;
    const int lsel = lane >> 3;

    const int bh = blockIdx.y;
    const int q0 = (gridDim.x - 1 - blockIdx.x) * 128;

    const unsigned* Qg = (const unsigned*)g_q + (size_t)bh * TT * HDIM;
    const unsigned* Kg = (const unsigned*)g_k + (size_t)bh * TT * HDIM;
    const unsigned* Vg = (const unsigned*)g_vt + (size_t)bh * HDIM * TT;

    const int rbase = w * 16 + fr;

    const uint32_t kvoff = (((lsel >> 1) * 8 + lrow) * ASTRIDE
                            + (lsel & 1) * 4) * 4;
    const uint32_t poff  = ((w * 16 + lrow + (lsel & 1) * 8) * ASTRIDE
                            + (lsel >> 1) * 4) * 4;

    unsigned aq[8][4];
    {
        const unsigned* q0p = Qg + (size_t)(q0 + rbase) * HDIM;
        const unsigned* q1p = q0p + 8 * HDIM;
#pragma unroll
        for (int kk = 0; kk < 8; kk++) {
            aq[kk][0] = q0p[kk * 8 + fc];
            aq[kk][1] = q1p[kk * 8 + fc];
            aq[kk][2] = q0p[kk * 8 + fc + 4];
            aq[kk][3] = q1p[kk * 8 + fc + 4];
        }
    }

    float O[8][4];
#pragma unroll
    for (int ni = 0; ni < 8; ni++)
#pragma unroll
        for (int e = 0; e < 4; e++) O[ni][e] = 0.f;
    float m_i[2] = {-1e30f, -1e30f};
    float l_i[2] = {0.f, 0.f};

    const int ntiles = (q0 >> 6) + 2;

    stage_kv(Kg, Vg, sb, tid, 0, 0);
    asm volatile("cp.async.commit_group;" ::: "memory");

    for (int kt = 0; kt < ntiles; kt++) {
        const int k0 = kt * 64;
        asm volatile("cp.async.wait_group 0;" ::: "memory");
        __syncthreads();

        if (kt + 1 < ntiles) {
            stage_kv(Kg, Vg, sb, tid, k0 + 64, (kt + 1) & 1);
            asm volatile("cp.async.commit_group;" ::: "memory");
        }

        const uint32_t Kbase = sb + (uint32_t)(kt & 1) * (KVBUF * 4);
        const uint32_t Vbase = Kbase + KVW * 4;

        float sacc[8][4];
#pragma unroll
        for (int ni = 0; ni < 8; ni++)
#pragma unroll
            for (int e = 0; e < 4; e++) sacc[ni][e] = 0.f;

#pragma unroll
        for (int kk = 0; kk < 8; kk++) {
#pragma unroll
            for (int np = 0; np < 4; np++) {
                unsigned t4[4];
                LDSM_X4(t4, Kbase + kvoff + (np * 16 * ASTRIDE + kk * 8) * 4);
                unsigned b0[2] = {t4[0], t4[1]};
                unsigned b1[2] = {t4[2], t4[3]};
                MMA_TF32(sacc[2 * np], aq[kk], b0);
                MMA_TF32(sacc[2 * np + 1], aq[kk], b1);
            }
        }

        const bool need_mask = (k0 + 63 > q0);
#pragma unroll
        for (int h = 0; h < 2; h++) {
            const int rg = q0 + rbase + h * 8;
            float rm = -1e30f;
#pragma unroll
            for (int ni = 0; ni < 8; ni++)
#pragma unroll
            for (int e = 0; e < 2; e++) {
                float s = sacc[ni][h * 2 + e];
                if (need_mask && (k0 + ni * 8 + fc * 2 + e > rg)) s = -1e30f;
                sacc[ni][h * 2 + e] = s;
                rm = fmaxf(rm, s);
            }
            rm = fmaxf(rm, __shfl_xor_sync(0xffffffffu, rm, 1));
            rm = fmaxf(rm, __shfl_xor_sync(0xffffffffu, rm, 2));
            float mnew = fmaxf(m_i[h], rm);
            float al = exp2_fast(m_i[h] - mnew);
            m_i[h] = mnew;
            float rs = 0.f;
#pragma unroll
            for (int ni = 0; ni < 8; ni++) {
                float p0 = exp2_fast(sacc[ni][h * 2 + 0] - mnew);
                float p1 = exp2_fast(sacc[ni][h * 2 + 1] - mnew);
                rs += p0 + p1;
                *(uint2*)&Ps[(rbase + h * 8) * ASTRIDE + ni * 8 + fc * 2] =
                    make_uint2(f2tf32(p0), f2tf32(p1));
            }
            rs += __shfl_xor_sync(0xffffffffu, rs, 1);
            rs += __shfl_xor_sync(0xffffffffu, rs, 2);
            l_i[h] = l_i[h] * al + rs;
#pragma unroll
            for (int ni = 0; ni < 8; ni++) {
                O[ni][h * 2 + 0] *= al;
                O[ni][h * 2 + 1] *= al;
            }
        }
        __syncwarp();

#pragma unroll
        for (int kk = 0; kk < 8; kk++) {
            unsigned af[4];
            LDSM_X4(af, psb + poff + kk * 8 * 4);
#pragma unroll
            for (int np = 0; np < 4; np++) {
                unsigned t4[4];
                LDSM_X4(t4, Vbase + kvoff + (np * 16 * ASTRIDE + kk * 8) * 4);
                unsigned b0[2] = {t4[0], t4[1]};
                unsigned b1[2] = {t4[2], t4[3]};
                MMA_TF32(O[2 * np], af, b0);
                MMA_TF32(O[2 * np + 1], af, b1);
            }
        }
    }

    const int b = bh >> 4;
    const int h = bh & 15;
#pragma unroll
    for (int hh = 0; hh < 2; hh++) {
        float linv = 1.0f / l_i[hh];
        int row = q0 + rbase + hh * 8;
        unsigned* op = (unsigned*)g_att + ((size_t)(b * TT) + row) * DIMC + h * HDIM;
#pragma unroll
        for (int ni = 0; ni < 8; ni++) {
            *(uint2*)(op + ni * 8 + fc * 2) =
                make_uint2(f2tf32(O[ni][hh * 2 + 0] * linv),
                           f2tf32(O[ni][hh * 2 + 1] * linv));
        }
    }
}

// ---------------------------------------------------------------------------
extern "C" void kernel_launch(void* const* d_in, const int* in_sizes, int n_in,
                              void* d_out, int out_size)
{
    const float* x  = (const float*)d_in[0];
    // d_in[1] = mask (unused; causal applied analytically)
    const float* wq = (const float*)d_in[2];
    const float* wk = (const float*)d_in[3];
    const float* wv = (const float*)d_in[4];
    const float* wo = (const float*)d_in[5];
    float* out = (float*)d_out;

    float *dq, *dk, *dvt, *datt;
    unsigned *dxc, *dwc;
    cudaGetSymbolAddress((void**)&dq,   g_q);
    cudaGetSymbolAddress((void**)&dk,   g_k);
    cudaGetSymbolAddress((void**)&dvt,  g_vt);
    cudaGetSymbolAddress((void**)&datt, g_att);
    cudaGetSymbolAddress((void**)&dxc,  g_xc);
    cudaGetSymbolAddress((void**)&dwc,  g_wc);

    cudaFuncSetAttribute(attn_kernel,
                         cudaFuncAttributeMaxDynamicSharedMemorySize,
                         ATTN_SMEM_BYTES);
    cudaFuncSetAttribute(attn_kernel,
                         cudaFuncAttributePreferredSharedMemoryCarveout, 100);
    cudaFuncSetAttribute(gemm_kernel,
                         cudaFuncAttributeMaxDynamicSharedMemorySize,
                         GSM_BYTES);
    cudaFuncSetAttribute(gemm_kernel,
                         cudaFuncAttributePreferredSharedMemoryCarveout, 100);

    // Prepass: round x + weights to tf32 (wq pre-scaled by 0.125*log2e)
    conv_in_kernel<<<(XF4 + 4 * WF4) / 256, 256>>>(x, wq, wk, wv, wo);

    // QKV projections (tf32-bit outputs; V transposed)
    gemm_kernel<<<dim3(8, 64, 3), 256, GSM_BYTES>>>(
        dxc, dwc, dwc + DIMC * DIMC, dwc + 2 * DIMC * DIMC,
        dq, dk, dvt, 1);

    // Flash attention: grid (16 q-tiles of 128, 64 b*h)
    attn_kernel<<<dim3(16, 64), 256, ATTN_SMEM_BYTES>>>();

    // Output projection (g_att holds tf32 bits)
    gemm_kernel<<<dim3(8, 64, 1), 256, GSM_BYTES>>>(
        (unsigned*)datt, dwc + 3 * DIMC * DIMC, nullptr, nullptr,
        out, nullptr, nullptr, 0);
}